// round 13
// baseline (speedup 1.0000x reference)
#include <cuda_runtime.h>
#include <cuda_fp16.h>
#include <math.h>
#include <stdint.h>

#define Nn 8192
#define Dd 512
#define KDIM 512
#define NHEADS 8
#define HDIM 64
#define TOPK 16
#define PSPLIT 32   // sim tile split: K1 = bi<32 (1552 tiles), K2 = 32<=bi<=bj (528)

// ---------------- scratch (static device globals; no allocation) -------------
__device__ float g_seq[2 * Nn * Dd];
__device__ float g_qkv[2 * Nn * 3 * Dd];
__device__ float g_att[2 * Nn * Dd];
__device__ float g_S[(size_t)Nn * Nn];
__device__ float g_hidden[Nn * (Dd / 2)];
__device__ uint16_t g_ah[2 * Nn * Dd];        // activations (fp16)
__device__ uint16_t g_a1h[Nn * Dd];           // proj1 act
__device__ uint16_t g_wp0h[Dd * Dd];
__device__ uint16_t g_wp1h[Dd * Dd];
__device__ uint16_t g_wqh[3 * Dd * Dd];
__device__ uint16_t g_woh[Dd * Dd];
__device__ uint16_t g_weh[(Dd / 2) * Dd];
__device__ uint16_t g_fh[Nn * Dd];            // fused (fp16)

// ============================ PTX helpers ====================================
__device__ __forceinline__ uint32_t smem_u32(const void* p) {
    uint32_t a;
    asm("{ .reg .u64 t; cvta.to.shared.u64 t, %1; cvt.u32.u64 %0, t; }" : "=r"(a) : "l"(p));
    return a;
}
__device__ __forceinline__ void cp16(uint32_t dst, const void* src) {
    asm volatile("cp.async.cg.shared.global [%0], [%1], 16;" :: "r"(dst), "l"(src) : "memory");
}
__device__ __forceinline__ void cp_commit() {
    asm volatile("cp.async.commit_group;" ::: "memory");
}
template <int N> __device__ __forceinline__ void cp_wait() {
    asm volatile("cp.async.wait_group %0;" :: "n"(N) : "memory");
}
__device__ __forceinline__ void ldsm4(uint32_t* r, uint32_t a) {
    asm volatile("ldmatrix.sync.aligned.m8n8.x4.shared.b16 {%0,%1,%2,%3}, [%4];"
                 : "=r"(r[0]), "=r"(r[1]), "=r"(r[2]), "=r"(r[3]) : "r"(a));
}
__device__ __forceinline__ void mma16816(float* c, const uint32_t* a, uint32_t b0, uint32_t b1) {
    asm volatile("mma.sync.aligned.m16n8k16.row.col.f32.f16.f16.f32 "
                 "{%0,%1,%2,%3}, {%4,%5,%6,%7}, {%8,%9}, {%0,%1,%2,%3};"
                 : "+f"(c[0]), "+f"(c[1]), "+f"(c[2]), "+f"(c[3])
                 : "r"(a[0]), "r"(a[1]), "r"(a[2]), "r"(a[3]), "r"(b0), "r"(b1));
}

// ======================= warp-MMA NT GEMM (fp16, fp32 acc) ===================
template <int RELU, int HAS_BIAS>
__global__ __launch_bounds__(128, 2) void tgemm(
    const uint16_t* __restrict__ Ap, const uint16_t* __restrict__ Bp,
    const float* __restrict__ bias, float* __restrict__ C, int ldc)
{
    __shared__ uint16_t sA[2][128 * 32];
    __shared__ uint16_t sB[2][128 * 32];

    const int tid = threadIdx.x;
    const int lane = tid & 31, wid = tid >> 5;
    const int wm = wid & 1;
    const int wn = wid >> 1;
    const int bm = blockIdx.y * 128, bn = blockIdx.x * 128;

    const uint32_t sa0 = smem_u32(&sA[0][0]), sa1 = smem_u32(&sA[1][0]);
    const uint32_t sb0 = smem_u32(&sB[0][0]), sb1 = smem_u32(&sB[1][0]);

    const int NCHK = KDIM / 32;

    uint32_t lsw[4]; size_t lsrc[4];
#pragma unroll
    for (int i = 0; i < 4; i++) {
        int s = tid + 128 * i;
        int r = s >> 2, c = s & 3;
        lsw[i] = r * 64 + (((c ^ ((r >> 1) & 3))) << 4);
        lsrc[i] = (size_t)r * KDIM + c * 8;
    }

    uint32_t offA[2][4], offB[2][4];
#pragma unroll
    for (int kk = 0; kk < 2; kk++) {
#pragma unroll
        for (int f = 0; f < 4; f++) {
            int r = wm * 64 + f * 16 + (lane & 15);
            int c = kk * 2 + (lane >> 4);
            offA[kk][f] = r * 64 + (((c ^ ((r >> 1) & 3))) << 4);
        }
#pragma unroll
        for (int g = 0; g < 4; g++) {
            int r = wn * 64 + g * 16 + (lane & 7) + ((lane >> 4) << 3);
            int c = kk * 2 + ((lane >> 3) & 1);
            offB[kk][g] = r * 64 + (((c ^ ((r >> 1) & 3))) << 4);
        }
    }

    float acc[4][8][4];
#pragma unroll
    for (int f = 0; f < 4; f++)
#pragma unroll
        for (int g = 0; g < 8; g++)
#pragma unroll
            for (int j = 0; j < 4; j++) acc[f][g][j] = 0.f;

    auto load_chunk = [&](int c, int buf) {
        const int k0 = c * 32;
        const uint32_t da = buf ? sa1 : sa0;
        const uint32_t db = buf ? sb1 : sb0;
#pragma unroll
        for (int i = 0; i < 4; i++) {
            cp16(da + lsw[i], Ap + (size_t)bm * KDIM + k0 + lsrc[i]);
            cp16(db + lsw[i], Bp + (size_t)bn * KDIM + k0 + lsrc[i]);
        }
        cp_commit();
    };

    load_chunk(0, 0);

    for (int c = 0; c < NCHK; c++) {
        const int b = c & 1;
        if (c + 1 < NCHK) { load_chunk(c + 1, b ^ 1); cp_wait<1>(); }
        else cp_wait<0>();
        __syncthreads();

        const uint32_t da = b ? sa1 : sa0;
        const uint32_t db = b ? sb1 : sb0;
#pragma unroll
        for (int kk = 0; kk < 2; kk++) {
            uint32_t ra[4][4], rb[4][4];
#pragma unroll
            for (int f = 0; f < 4; f++) ldsm4(ra[f], da + offA[kk][f]);
#pragma unroll
            for (int g = 0; g < 4; g++) ldsm4(rb[g], db + offB[kk][g]);
#pragma unroll
            for (int f = 0; f < 4; f++)
#pragma unroll
                for (int g = 0; g < 4; g++) {
                    mma16816(acc[f][2 * g + 0], ra[f], rb[g][0], rb[g][1]);
                    mma16816(acc[f][2 * g + 1], ra[f], rb[g][2], rb[g][3]);
                }
        }
        __syncthreads();
    }

    const int col0 = bn + wn * 64 + (lane & 3) * 2;
#pragma unroll
    for (int f = 0; f < 4; f++) {
        const int row0 = bm + wm * 64 + f * 16 + (lane >> 2);
#pragma unroll
        for (int g = 0; g < 8; g++) {
            const int col = col0 + g * 8;
            float b0 = 0.f, b1 = 0.f;
            if (HAS_BIAS) { b0 = bias[col]; b1 = bias[col + 1]; }
            float2 v0, v1;
            v0.x = acc[f][g][0] + b0; v0.y = acc[f][g][1] + b1;
            v1.x = acc[f][g][2] + b0; v1.y = acc[f][g][3] + b1;
            if (RELU) {
                v0.x = fmaxf(v0.x, 0.f); v0.y = fmaxf(v0.y, 0.f);
                v1.x = fmaxf(v1.x, 0.f); v1.y = fmaxf(v1.y, 0.f);
            }
            *(float2*)(C + (size_t)row0 * ldc + col) = v0;
            *(float2*)(C + (size_t)(row0 + 8) * ldc + col) = v1;
        }
    }
}

// ============== symmetric variant: S = F*F^T, upper-triangle blocks ==========
// PART 0: tiles with bi < PSPLIT  (completes S rows [0, PSPLIT*128) incl mirrors)
// PART 1: sub-triangle bi,bj >= PSPLIT
template <int PART>
__global__ __launch_bounds__(128, 2) void tgemm_sym(
    const uint16_t* __restrict__ Fp, float* __restrict__ C)
{
    __shared__ __align__(16) uint8_t smraw[32768];
    float* smT = (float*)smraw;

    const int tid = threadIdx.x;
    const int lane = tid & 31, wid = tid >> 5;
    const int wm = wid & 1;
    const int wn = wid >> 1;

    int bi, bj;
    if (PART == 0) {
        int rem = blockIdx.x;
        bi = 0;
        while (rem >= 64 - bi) { rem -= 64 - bi; bi++; }
        bj = bi + rem;
    } else {
        int t = blockIdx.x;
        int bj2 = (int)((sqrtf(8.f * t + 1.f) - 1.f) * 0.5f);
        while ((bj2 + 1) * (bj2 + 2) / 2 <= t) bj2++;
        while (bj2 * (bj2 + 1) / 2 > t) bj2--;
        int bi2 = t - bj2 * (bj2 + 1) / 2;
        bi = PSPLIT + bi2;
        bj = PSPLIT + bj2;
    }
    const int bm = bi * 128, bn = bj * 128;

    const uint32_t sa0 = smem_u32(smraw), sa1 = smem_u32(smraw + 8192);
    const uint32_t sb0 = smem_u32(smraw + 16384), sb1 = smem_u32(smraw + 24576);

    const int NCHK = KDIM / 32;

    uint32_t lsw[4]; size_t lsrc[4];
#pragma unroll
    for (int i = 0; i < 4; i++) {
        int s = tid + 128 * i;
        int r = s >> 2, c = s & 3;
        lsw[i] = r * 64 + (((c ^ ((r >> 1) & 3))) << 4);
        lsrc[i] = (size_t)r * KDIM + c * 8;
    }

    uint32_t offA[2][4], offB[2][4];
#pragma unroll
    for (int kk = 0; kk < 2; kk++) {
#pragma unroll
        for (int f = 0; f < 4; f++) {
            int r = wm * 64 + f * 16 + (lane & 15);
            int c = kk * 2 + (lane >> 4);
            offA[kk][f] = r * 64 + (((c ^ ((r >> 1) & 3))) << 4);
        }
#pragma unroll
        for (int g = 0; g < 4; g++) {
            int r = wn * 64 + g * 16 + (lane & 7) + ((lane >> 4) << 3);
            int c = kk * 2 + ((lane >> 3) & 1);
            offB[kk][g] = r * 64 + (((c ^ ((r >> 1) & 3))) << 4);
        }
    }

    float acc[4][8][4];
#pragma unroll
    for (int f = 0; f < 4; f++)
#pragma unroll
        for (int g = 0; g < 8; g++)
#pragma unroll
            for (int j = 0; j < 4; j++) acc[f][g][j] = 0.f;

    auto load_chunk = [&](int c, int buf) {
        const int k0 = c * 32;
        const uint32_t da = buf ? sa1 : sa0;
        const uint32_t db = buf ? sb1 : sb0;
#pragma unroll
        for (int i = 0; i < 4; i++) {
            cp16(da + lsw[i], Fp + (size_t)bm * KDIM + k0 + lsrc[i]);
            cp16(db + lsw[i], Fp + (size_t)bn * KDIM + k0 + lsrc[i]);
        }
        cp_commit();
    };

    load_chunk(0, 0);

    for (int c = 0; c < NCHK; c++) {
        const int b = c & 1;
        if (c + 1 < NCHK) { load_chunk(c + 1, b ^ 1); cp_wait<1>(); }
        else cp_wait<0>();
        __syncthreads();

        const uint32_t da = b ? sa1 : sa0;
        const uint32_t db = b ? sb1 : sb0;
#pragma unroll
        for (int kk = 0; kk < 2; kk++) {
            uint32_t ra[4][4], rb[4][4];
#pragma unroll
            for (int f = 0; f < 4; f++) ldsm4(ra[f], da + offA[kk][f]);
#pragma unroll
            for (int g = 0; g < 4; g++) ldsm4(rb[g], db + offB[kk][g]);
#pragma unroll
            for (int f = 0; f < 4; f++)
#pragma unroll
                for (int g = 0; g < 4; g++) {
                    mma16816(acc[f][2 * g + 0], ra[f], rb[g][0], rb[g][1]);
                    mma16816(acc[f][2 * g + 1], ra[f], rb[g][2], rb[g][3]);
                }
        }
        __syncthreads();
    }

    const int col0 = bn + wn * 64 + (lane & 3) * 2;
#pragma unroll
    for (int f = 0; f < 4; f++) {
        const int row0 = bm + wm * 64 + f * 16 + (lane >> 2);
#pragma unroll
        for (int g = 0; g < 8; g++) {
            const int col = col0 + g * 8;
            float2 v0, v1;
            v0.x = acc[f][g][0]; v0.y = acc[f][g][1];
            v1.x = acc[f][g][2]; v1.y = acc[f][g][3];
            *(float2*)(C + (size_t)row0 * Nn + col) = v0;
            *(float2*)(C + (size_t)(row0 + 8) * Nn + col) = v1;
        }
    }

    if (bi != bj) {
#pragma unroll
        for (int cc = 0; cc < 2; cc++) {
            __syncthreads();
            float* buf = smT + wn * (32 * 128);
#pragma unroll
            for (int gl = 0; gl < 4; gl++) {
                const int g = cc * 4 + gl;
                const int cl = gl * 8 + (lane & 3) * 2;
#pragma unroll
                for (int f = 0; f < 4; f++) {
                    const int r = wm * 64 + f * 16 + (lane >> 2);
                    buf[cl * 128 + r]           = acc[f][g][0];
                    buf[(cl + 1) * 128 + r]     = acc[f][g][1];
                    buf[cl * 128 + r + 8]       = acc[f][g][2];
                    buf[(cl + 1) * 128 + r + 8] = acc[f][g][3];
                }
            }
            __syncthreads();
            for (int idx = tid; idx < 64 * 32; idx += 128) {
                const int rr = idx >> 5;
                const int sg = idx & 31;
                const int b2 = rr >> 5;
                const int cl = rr & 31;
                const int cAbs = bn + b2 * 64 + cc * 32 + cl;
                float4 v = *(float4*)(smT + b2 * (32 * 128) + cl * 128 + sg * 4);
                *(float4*)(C + (size_t)cAbs * Nn + bm + sg * 4) = v;
            }
        }
    }
}

// ---------------- fp32 -> fp16 convert ---------------------------------------
__global__ void split_kernel(const float* __restrict__ x, uint16_t* __restrict__ hi,
                             int n4)
{
    int i = blockIdx.x * blockDim.x + threadIdx.x;
    if (i >= n4) return;
    float4 v = ((const float4*)x)[i];
    ushort4 hv;
    hv.x = __half_as_ushort(__float2half_rn(v.x));
    hv.y = __half_as_ushort(__float2half_rn(v.y));
    hv.z = __half_as_ushort(__float2half_rn(v.z));
    hv.w = __half_as_ushort(__float2half_rn(v.w));
    ((ushort4*)hi)[i] = hv;
}

// ---------------- LayerNorm -> fp16 directly ---------------------------------
__global__ void ln_kernel(const float* __restrict__ g0, const float* __restrict__ be0,
                          const float* __restrict__ g1, const float* __restrict__ be1)
{
    int row = blockIdx.x;
    const float* x = g_seq + (size_t)row * Dd;
    int tid = threadIdx.x;
    float v0 = x[tid], v1 = x[tid + 256];
    __shared__ float rs[256], rq[256];
    rs[tid] = v0 + v1;
    rq[tid] = v0 * v0 + v1 * v1;
    __syncthreads();
    for (int st = 128; st > 0; st >>= 1) {
        if (tid < st) { rs[tid] += rs[tid + st]; rq[tid] += rq[tid + st]; }
        __syncthreads();
    }
    float mean = rs[0] * (1.f / Dd);
    float var = rq[0] * (1.f / Dd) - mean * mean;
    float inv = rsqrtf(var + 1e-5f);
    const float* gg = (row & 1) ? g1 : g0;
    const float* bb = (row & 1) ? be1 : be0;
    float y0 = (v0 - mean) * inv * gg[tid] + bb[tid];
    float y1 = (v1 - mean) * inv * gg[tid + 256] + bb[tid + 256];
    size_t base = (size_t)row * Dd;
    g_ah[base + tid]       = __half_as_ushort(__float2half_rn(y0));
    g_ah[base + tid + 256] = __half_as_ushort(__float2half_rn(y1));
}

// ---------------- 2-token multihead attention -> ctx fp16 --------------------
__global__ void attn_kernel()
{
    int gt = blockIdx.x * blockDim.x + threadIdx.x;
    int gw = gt >> 5, lane = gt & 31;
    if (gw >= Nn * NHEADS) return;
    int node = gw >> 3, h = gw & 7;
    const float* base = g_qkv + (size_t)node * 2 * (3 * Dd);
    int d0 = lane * 2;
    float q[2][2], k[2][2], v[2][2];
#pragma unroll
    for (int t = 0; t < 2; t++) {
        const float* r = base + t * (3 * Dd) + h * HDIM;
        float2 qq = *(const float2*)(r + d0);
        float2 kk = *(const float2*)(r + Dd + d0);
        float2 vv = *(const float2*)(r + 2 * Dd + d0);
        q[t][0] = qq.x; q[t][1] = qq.y;
        k[t][0] = kk.x; k[t][1] = kk.y;
        v[t][0] = vv.x; v[t][1] = vv.y;
    }
    float s[2][2];
#pragma unroll
    for (int qi = 0; qi < 2; qi++)
#pragma unroll
        for (int ki = 0; ki < 2; ki++)
            s[qi][ki] = q[qi][0] * k[ki][0] + q[qi][1] * k[ki][1];
#pragma unroll
    for (int o = 16; o > 0; o >>= 1)
#pragma unroll
        for (int qi = 0; qi < 2; qi++)
#pragma unroll
            for (int ki = 0; ki < 2; ki++)
                s[qi][ki] += __shfl_xor_sync(0xffffffffu, s[qi][ki], o);
    const float scale = 0.125f;
#pragma unroll
    for (int qi = 0; qi < 2; qi++) {
        float a0 = s[qi][0] * scale, a1 = s[qi][1] * scale;
        float m = fmaxf(a0, a1);
        float e0 = __expf(a0 - m), e1 = __expf(a1 - m);
        float inv = 1.f / (e0 + e1);
        float w0 = e0 * inv, w1 = e1 * inv;
        float o0 = w0 * v[0][0] + w1 * v[1][0];
        float o1 = w0 * v[0][1] + w1 * v[1][1];
        size_t off = (size_t)(node * 2 + qi) * Dd + h * HDIM + d0;
        ushort2 hv;
        hv.x = __half_as_ushort(__float2half_rn(o0));
        hv.y = __half_as_ushort(__float2half_rn(o1));
        *(ushort2*)(g_ah + off) = hv;
    }
}

// ---------------- mean over the 2 tokens -> fused fp16 -----------------------
__global__ void mean_kernel()
{
    int i = blockIdx.x * blockDim.x + threadIdx.x;
    if (i >= Nn * Dd / 4) return;
    int e0 = i * 4;
    int node = e0 / Dd, d = e0 - node * Dd;
    const float* r0 = g_att + (size_t)(node * 2) * Dd + d;
    const float* r1 = g_att + (size_t)(node * 2 + 1) * Dd + d;
    float4 a = *(const float4*)r0, b = *(const float4*)r1;
    ushort4 hv;
    hv.x = __half_as_ushort(__float2half_rn(0.5f * (a.x + b.x)));
    hv.y = __half_as_ushort(__float2half_rn(0.5f * (a.y + b.y)));
    hv.z = __half_as_ushort(__float2half_rn(0.5f * (a.z + b.z)));
    hv.w = __half_as_ushort(__float2half_rn(0.5f * (a.w + b.w)));
    ((ushort4*)g_fh)[i] = hv;
}

// ---------------- softmax stats + top-16 via segment-max hierarchy ----------
__global__ void topk_kernel(float* __restrict__ Hout, int row0)
{
    int row = blockIdx.x + row0;
    extern __shared__ float sh[];                 // Nn floats + 256 segmax
    float* segmax = sh + Nn;
    __shared__ float swv[8];
    __shared__ int swi[8];
    __shared__ float s_bcast;
    __shared__ int s_seg;
    __shared__ float topv[TOPK];
    __shared__ int topi[TOPK];
    const float* srow = g_S + (size_t)row * Nn;
    int tid = threadIdx.x;
    int lane = tid & 31, wid = tid >> 5;

    // vectorized row load (float4)
    for (int j4 = tid; j4 < Nn / 4; j4 += 256)
        *(float4*)(sh + j4 * 4) = ((const float4*)srow)[j4];
    __syncthreads();

    {
        const int base = tid * 32;
        float sm = -INFINITY;
#pragma unroll 8
        for (int i = 0; i < 32; i++)
            sm = fmaxf(sm, sh[base + ((i + tid) & 31)]);
        segmax[tid] = sm;
        float lmax = sm;
#pragma unroll
        for (int o = 16; o > 0; o >>= 1)
            lmax = fmaxf(lmax, __shfl_xor_sync(0xffffffffu, lmax, o));
        if (lane == 0) swv[wid] = lmax;
    }
    __syncthreads();
    if (tid == 0) {
        float m = swv[0];
#pragma unroll
        for (int w = 1; w < 8; w++) m = fmaxf(m, swv[w]);
        s_bcast = m;
    }
    __syncthreads();
    const float rmax = s_bcast;

    float lsum = 0.f;
    for (int j4 = tid; j4 < Nn / 4; j4 += 256) {
        float4 v = *(float4*)(sh + j4 * 4);
        lsum += __expf(v.x - rmax) + __expf(v.y - rmax)
              + __expf(v.z - rmax) + __expf(v.w - rmax);
    }
#pragma unroll
    for (int o = 16; o > 0; o >>= 1)
        lsum += __shfl_xor_sync(0xffffffffu, lsum, o);
    if (lane == 0) swv[wid] = lsum;
    __syncthreads();
    if (tid == 0) {
        float s = 0.f;
#pragma unroll
        for (int w = 0; w < 8; w++) s += swv[w];
        s_bcast = 1.f / s;
    }
    __syncthreads();
    const float rinv = s_bcast;

    for (int kk = 0; kk < TOPK; kk++) {
        float v = segmax[tid];
        int idx = tid;
#pragma unroll
        for (int o = 16; o > 0; o >>= 1) {
            float ov = __shfl_xor_sync(0xffffffffu, v, o);
            int oi = __shfl_xor_sync(0xffffffffu, idx, o);
            if (ov > v || (ov == v && oi < idx)) { v = ov; idx = oi; }
        }
        if (lane == 0) { swv[wid] = v; swi[wid] = idx; }
        __syncthreads();
        if (tid == 0) {
            float bv = swv[0]; int bi = swi[0];
#pragma unroll
            for (int w = 1; w < 8; w++)
                if (swv[w] > bv || (swv[w] == bv && swi[w] < bi)) { bv = swv[w]; bi = swi[w]; }
            s_seg = bi;
        }
        __syncthreads();
        const int s = s_seg;
        if (wid == 0) {
            int ei = s * 32 + lane;
            float ev = sh[ei];
            float v2 = ev; int i2 = ei;
#pragma unroll
            for (int o = 16; o > 0; o >>= 1) {
                float ov = __shfl_xor_sync(0xffffffffu, v2, o);
                int oi = __shfl_xor_sync(0xffffffffu, i2, o);
                if (ov > v2 || (ov == v2 && oi < i2)) { v2 = ov; i2 = oi; }
            }
            if (lane == 0) { topv[kk] = v2; topi[kk] = i2; }
            float nv = (ei == i2) ? -INFINITY : ev;
            if (ei == i2) sh[ei] = -INFINITY;
            float mx = nv;
#pragma unroll
            for (int o = 16; o > 0; o >>= 1)
                mx = fmaxf(mx, __shfl_xor_sync(0xffffffffu, mx, o));
            if (lane == 0) segmax[s] = mx;
        }
        __syncthreads();
    }

    if (tid == 0) {
        Hout[(size_t)row * Nn + row] = 1.0f;
#pragma unroll
        for (int kk = 0; kk < TOPK; kk++)
            Hout[(size_t)topi[kk] * Nn + row] = __expf(topv[kk] - rmax) * rinv;
    }
}

__global__ void ew_kernel(const float* __restrict__ w2, const float* __restrict__ b2,
                          float* __restrict__ out)
{
    int gt = blockIdx.x * blockDim.x + threadIdx.x;
    int gw = gt >> 5, lane = gt & 31;
    if (gw >= Nn) return;
    const float* hrow = g_hidden + (size_t)gw * (Dd / 2);
    float s = 0.f;
    for (int j = lane; j < Dd / 2; j += 32) s += hrow[j] * w2[j];
#pragma unroll
    for (int o = 16; o > 0; o >>= 1) s += __shfl_xor_sync(0xffffffffu, s, o);
    if (lane == 0) {
        float v = s + b2[0];
        float sig = 1.f / (1.f + __expf(-v));
        out[gw] = fmaxf(sig, 1e-8f);
    }
}

// ---------------- launch ------------------------------------------------------
static void do_split_s(const float* src, uint16_t* hi, size_t n, cudaStream_t st)
{
    int n4 = (int)(n / 4);
    split_kernel<<<(n4 + 255) / 256, 256, 0, st>>>(src, hi, n4);
}

extern "C" void kernel_launch(void* const* d_in, const int* in_sizes, int n_in,
                              void* d_out, int out_size)
{
    const float* x0    = (const float*)d_in[0];
    const float* x1    = (const float*)d_in[1];
    const float* w_p0  = (const float*)d_in[2];
    const float* b_p0  = (const float*)d_in[3];
    const float* gg0   = (const float*)d_in[4];
    const float* be0   = (const float*)d_in[5];
    const float* w_p1  = (const float*)d_in[6];
    const float* b_p1  = (const float*)d_in[7];
    const float* gg1   = (const float*)d_in[8];
    const float* be1   = (const float*)d_in[9];
    const float* in_w  = (const float*)d_in[10];
    const float* in_b  = (const float*)d_in[11];
    const float* out_w = (const float*)d_in[12];
    const float* out_b = (const float*)d_in[13];
    const float* ew_w1 = (const float*)d_in[14];
    const float* ew_b1 = (const float*)d_in[15];
    const float* ew_w2 = (const float*)d_in[16];
    const float* ew_b2 = (const float*)d_in[17];

    float* H  = (float*)d_out;
    float* ew = H + (size_t)Nn * Nn;

    float *seq, *qkv, *att, *S, *hidden;
    uint16_t *ah, *a1h, *fh;
    uint16_t *wp0h, *wp1h, *wqh, *woh, *weh;
    cudaGetSymbolAddress((void**)&seq, g_seq);
    cudaGetSymbolAddress((void**)&qkv, g_qkv);
    cudaGetSymbolAddress((void**)&att, g_att);
    cudaGetSymbolAddress((void**)&S, g_S);
    cudaGetSymbolAddress((void**)&hidden, g_hidden);
    cudaGetSymbolAddress((void**)&ah, g_ah);
    cudaGetSymbolAddress((void**)&a1h, g_a1h);
    cudaGetSymbolAddress((void**)&wp0h, g_wp0h);
    cudaGetSymbolAddress((void**)&wp1h, g_wp1h);
    cudaGetSymbolAddress((void**)&wqh, g_wqh);
    cudaGetSymbolAddress((void**)&woh, g_woh);
    cudaGetSymbolAddress((void**)&weh, g_weh);
    cudaGetSymbolAddress((void**)&fh, g_fh);

    static cudaStream_t s1 = nullptr, s2 = nullptr;
    static cudaEvent_t eF = nullptr, eS2 = nullptr, eP1 = nullptr, eM = nullptr,
                       eE = nullptr, eK1 = nullptr, eT1 = nullptr;
    if (!s1) {
        cudaStreamCreateWithFlags(&s1, cudaStreamNonBlocking);
        cudaStreamCreateWithFlags(&s2, cudaStreamNonBlocking);
        cudaEventCreateWithFlags(&eF,  cudaEventDisableTiming);
        cudaEventCreateWithFlags(&eS2, cudaEventDisableTiming);
        cudaEventCreateWithFlags(&eP1, cudaEventDisableTiming);
        cudaEventCreateWithFlags(&eM,  cudaEventDisableTiming);
        cudaEventCreateWithFlags(&eE,  cudaEventDisableTiming);
        cudaEventCreateWithFlags(&eK1, cudaEventDisableTiming);
        cudaEventCreateWithFlags(&eT1, cudaEventDisableTiming);
    }

    // fork from capture (default) stream
    cudaEventRecord(eF, 0);
    cudaStreamWaitEvent(s1, eF, 0);
    cudaStreamWaitEvent(s2, eF, 0);

    // s2: H memset + weight converts (input-only)
    cudaMemsetAsync(H, 0, (size_t)Nn * Nn * sizeof(float), s2);
    do_split_s(in_w,  wqh, (size_t)3 * Dd * Dd, s2);
    do_split_s(out_w, woh, (size_t)Dd * Dd, s2);
    do_split_s(ew_w1, weh, (size_t)(Dd / 2) * Dd, s2);
    cudaEventRecord(eS2, s2);

    // s1: modality-1 projection chain
    do_split_s(x1,   a1h,  (size_t)Nn * Dd, s1);
    do_split_s(w_p1, wp1h, (size_t)Dd * Dd, s1);
    tgemm<1, 1><<<dim3(Dd / 128, Nn / 128), 128, 0, s1>>>(a1h, wp1h, b_p1, seq + Dd, 2 * Dd);
    cudaEventRecord(eP1, s1);

    // stream 0: modality-0 projection chain
    do_split_s(x0,   ah,   (size_t)Nn * Dd, 0);
    do_split_s(w_p0, wp0h, (size_t)Dd * Dd, 0);
    tgemm<1, 1><<<dim3(Dd / 128, Nn / 128), 128>>>(ah, wp0h, b_p0, seq, 2 * Dd);

    // join proj1 + weight converts, trunk on stream 0
    cudaStreamWaitEvent(0, eP1, 0);
    ln_kernel<<<2 * Nn, 256>>>(gg0, be0, gg1, be1);
    cudaStreamWaitEvent(0, eS2, 0);
    tgemm<0, 1><<<dim3(3 * Dd / 128, 2 * Nn / 128), 128>>>(ah, wqh, in_b, qkv, 3 * Dd);
    attn_kernel<<<(Nn * NHEADS * 32) / 256, 256>>>();
    tgemm<0, 1><<<dim3(Dd / 128, 2 * Nn / 128), 128>>>(ah, woh, out_b, att, Dd);
    mean_kernel<<<(Nn * Dd / 4 + 255) / 256, 256>>>();
    cudaEventRecord(eM, 0);

    // s1: edge-weight MLP (parallel to sim GEMM + topk)
    cudaStreamWaitEvent(s1, eM, 0);
    tgemm<1, 1><<<dim3((Dd / 2) / 128, Nn / 128), 128, 0, s1>>>(fh, weh, ew_b1, hidden, Dd / 2);
    ew_kernel<<<(Nn * 32) / 256, 256, 0, s1>>>(ew_w2, ew_b2, ew);
    cudaEventRecord(eE, s1);

    // stream 0: sim GEMM part 1 (bi < PSPLIT -> S rows [0, 4096) complete)
    const int NT1 = PSPLIT * 64 - PSPLIT * (PSPLIT - 1) / 2;   // 1552
    const int NT2 = (64 - PSPLIT) * (64 - PSPLIT + 1) / 2;     // 528
    tgemm_sym<0><<<NT1, 128>>>(fh, S);
    cudaEventRecord(eK1, 0);

    // s2: topk on rows [0, 4096) overlapped with sim part 2
    cudaStreamWaitEvent(s2, eK1, 0);
    topk_kernel<<<PSPLIT * 128, 256, (Nn + 256) * sizeof(float), s2>>>(H, 0);
    cudaEventRecord(eT1, s2);

    // stream 0: sim GEMM part 2, then topk on rows [4096, 8192)
    tgemm_sym<1><<<NT2, 128>>>(fh, S);
    topk_kernel<<<(64 - PSPLIT) * 128, 256, (Nn + 256) * sizeof(float)>>>(H, PSPLIT * 128);

    // joins
    cudaStreamWaitEvent(0, eT1, 0);
    cudaStreamWaitEvent(0, eE, 0);
}

// round 14
// speedup vs baseline: 1.5377x; 1.5377x over previous
#include <cuda_runtime.h>
#include <cuda_fp16.h>
#include <math.h>
#include <stdint.h>

#define Nn 8192
#define Dd 512
#define KDIM 512
#define NHEADS 8
#define HDIM 64
#define TOPK 16

// ---------------- scratch (static device globals; no allocation) -------------
__device__ float g_seq[2 * Nn * Dd];
__device__ float g_qkv[2 * Nn * 3 * Dd];
__device__ float g_att[2 * Nn * Dd];
__device__ float g_S[(size_t)Nn * Nn];
__device__ float g_hidden[Nn * (Dd / 2)];
__device__ uint16_t g_ah[2 * Nn * Dd];        // activations (fp16)
__device__ uint16_t g_a1h[Nn * Dd];           // proj1 act
__device__ uint16_t g_wp0h[Dd * Dd];
__device__ uint16_t g_wp1h[Dd * Dd];
__device__ uint16_t g_wqh[3 * Dd * Dd];
__device__ uint16_t g_woh[Dd * Dd];
__device__ uint16_t g_weh[(Dd / 2) * Dd];
__device__ uint16_t g_fh[Nn * Dd];            // fused (fp16)

// ============================ PTX helpers ====================================
__device__ __forceinline__ uint32_t smem_u32(const void* p) {
    uint32_t a;
    asm("{ .reg .u64 t; cvta.to.shared.u64 t, %1; cvt.u32.u64 %0, t; }" : "=r"(a) : "l"(p));
    return a;
}
__device__ __forceinline__ void cp16(uint32_t dst, const void* src) {
    asm volatile("cp.async.cg.shared.global [%0], [%1], 16;" :: "r"(dst), "l"(src) : "memory");
}
__device__ __forceinline__ void cp_commit() {
    asm volatile("cp.async.commit_group;" ::: "memory");
}
template <int N> __device__ __forceinline__ void cp_wait() {
    asm volatile("cp.async.wait_group %0;" :: "n"(N) : "memory");
}
__device__ __forceinline__ void ldsm4(uint32_t* r, uint32_t a) {
    asm volatile("ldmatrix.sync.aligned.m8n8.x4.shared.b16 {%0,%1,%2,%3}, [%4];"
                 : "=r"(r[0]), "=r"(r[1]), "=r"(r[2]), "=r"(r[3]) : "r"(a));
}
__device__ __forceinline__ void mma16816(float* c, const uint32_t* a, uint32_t b0, uint32_t b1) {
    asm volatile("mma.sync.aligned.m16n8k16.row.col.f32.f16.f16.f32 "
                 "{%0,%1,%2,%3}, {%4,%5,%6,%7}, {%8,%9}, {%0,%1,%2,%3};"
                 : "+f"(c[0]), "+f"(c[1]), "+f"(c[2]), "+f"(c[3])
                 : "r"(a[0]), "r"(a[1]), "r"(a[2]), "r"(a[3]), "r"(b0), "r"(b1));
}

// ======================= warp-MMA NT GEMM (fp16, fp32 acc) ===================
template <int RELU, int HAS_BIAS>
__global__ __launch_bounds__(128, 2) void tgemm(
    const uint16_t* __restrict__ Ap, const uint16_t* __restrict__ Bp,
    const float* __restrict__ bias, float* __restrict__ C, int ldc)
{
    __shared__ uint16_t sA[2][128 * 32];
    __shared__ uint16_t sB[2][128 * 32];

    const int tid = threadIdx.x;
    const int lane = tid & 31, wid = tid >> 5;
    const int wm = wid & 1;
    const int wn = wid >> 1;
    const int bm = blockIdx.y * 128, bn = blockIdx.x * 128;

    const uint32_t sa0 = smem_u32(&sA[0][0]), sa1 = smem_u32(&sA[1][0]);
    const uint32_t sb0 = smem_u32(&sB[0][0]), sb1 = smem_u32(&sB[1][0]);

    const int NCHK = KDIM / 32;

    uint32_t lsw[4]; size_t lsrc[4];
#pragma unroll
    for (int i = 0; i < 4; i++) {
        int s = tid + 128 * i;
        int r = s >> 2, c = s & 3;
        lsw[i] = r * 64 + (((c ^ ((r >> 1) & 3))) << 4);
        lsrc[i] = (size_t)r * KDIM + c * 8;
    }

    uint32_t offA[2][4], offB[2][4];
#pragma unroll
    for (int kk = 0; kk < 2; kk++) {
#pragma unroll
        for (int f = 0; f < 4; f++) {
            int r = wm * 64 + f * 16 + (lane & 15);
            int c = kk * 2 + (lane >> 4);
            offA[kk][f] = r * 64 + (((c ^ ((r >> 1) & 3))) << 4);
        }
#pragma unroll
        for (int g = 0; g < 4; g++) {
            int r = wn * 64 + g * 16 + (lane & 7) + ((lane >> 4) << 3);
            int c = kk * 2 + ((lane >> 3) & 1);
            offB[kk][g] = r * 64 + (((c ^ ((r >> 1) & 3))) << 4);
        }
    }

    float acc[4][8][4];
#pragma unroll
    for (int f = 0; f < 4; f++)
#pragma unroll
        for (int g = 0; g < 8; g++)
#pragma unroll
            for (int j = 0; j < 4; j++) acc[f][g][j] = 0.f;

    auto load_chunk = [&](int c, int buf) {
        const int k0 = c * 32;
        const uint32_t da = buf ? sa1 : sa0;
        const uint32_t db = buf ? sb1 : sb0;
#pragma unroll
        for (int i = 0; i < 4; i++) {
            cp16(da + lsw[i], Ap + (size_t)bm * KDIM + k0 + lsrc[i]);
            cp16(db + lsw[i], Bp + (size_t)bn * KDIM + k0 + lsrc[i]);
        }
        cp_commit();
    };

    load_chunk(0, 0);

    for (int c = 0; c < NCHK; c++) {
        const int b = c & 1;
        if (c + 1 < NCHK) { load_chunk(c + 1, b ^ 1); cp_wait<1>(); }
        else cp_wait<0>();
        __syncthreads();

        const uint32_t da = b ? sa1 : sa0;
        const uint32_t db = b ? sb1 : sb0;
#pragma unroll
        for (int kk = 0; kk < 2; kk++) {
            uint32_t ra[4][4], rb[4][4];
#pragma unroll
            for (int f = 0; f < 4; f++) ldsm4(ra[f], da + offA[kk][f]);
#pragma unroll
            for (int g = 0; g < 4; g++) ldsm4(rb[g], db + offB[kk][g]);
#pragma unroll
            for (int f = 0; f < 4; f++)
#pragma unroll
                for (int g = 0; g < 4; g++) {
                    mma16816(acc[f][2 * g + 0], ra[f], rb[g][0], rb[g][1]);
                    mma16816(acc[f][2 * g + 1], ra[f], rb[g][2], rb[g][3]);
                }
        }
        __syncthreads();
    }

    const int col0 = bn + wn * 64 + (lane & 3) * 2;
#pragma unroll
    for (int f = 0; f < 4; f++) {
        const int row0 = bm + wm * 64 + f * 16 + (lane >> 2);
#pragma unroll
        for (int g = 0; g < 8; g++) {
            const int col = col0 + g * 8;
            float b0 = 0.f, b1 = 0.f;
            if (HAS_BIAS) { b0 = bias[col]; b1 = bias[col + 1]; }
            float2 v0, v1;
            v0.x = acc[f][g][0] + b0; v0.y = acc[f][g][1] + b1;
            v1.x = acc[f][g][2] + b0; v1.y = acc[f][g][3] + b1;
            if (RELU) {
                v0.x = fmaxf(v0.x, 0.f); v0.y = fmaxf(v0.y, 0.f);
                v1.x = fmaxf(v1.x, 0.f); v1.y = fmaxf(v1.y, 0.f);
            }
            *(float2*)(C + (size_t)row0 * ldc + col) = v0;
            *(float2*)(C + (size_t)(row0 + 8) * ldc + col) = v1;
        }
    }
}

// ============== symmetric variant: S = F*F^T, upper-triangle blocks ==========
__global__ __launch_bounds__(128, 2) void tgemm_sym(
    const uint16_t* __restrict__ Fp, float* __restrict__ C)
{
    __shared__ __align__(16) uint8_t smraw[32768];
    float* smT = (float*)smraw;

    const int tid = threadIdx.x;
    const int lane = tid & 31, wid = tid >> 5;
    const int wm = wid & 1;
    const int wn = wid >> 1;

    int t = blockIdx.x;
    int bj = (int)((sqrtf(8.f * t + 1.f) - 1.f) * 0.5f);
    while ((bj + 1) * (bj + 2) / 2 <= t) bj++;
    while (bj * (bj + 1) / 2 > t) bj--;
    int bi = t - bj * (bj + 1) / 2;
    const int bm = bi * 128, bn = bj * 128;

    const uint32_t sa0 = smem_u32(smraw), sa1 = smem_u32(smraw + 8192);
    const uint32_t sb0 = smem_u32(smraw + 16384), sb1 = smem_u32(smraw + 24576);

    const int NCHK = KDIM / 32;

    uint32_t lsw[4]; size_t lsrc[4];
#pragma unroll
    for (int i = 0; i < 4; i++) {
        int s = tid + 128 * i;
        int r = s >> 2, c = s & 3;
        lsw[i] = r * 64 + (((c ^ ((r >> 1) & 3))) << 4);
        lsrc[i] = (size_t)r * KDIM + c * 8;
    }

    uint32_t offA[2][4], offB[2][4];
#pragma unroll
    for (int kk = 0; kk < 2; kk++) {
#pragma unroll
        for (int f = 0; f < 4; f++) {
            int r = wm * 64 + f * 16 + (lane & 15);
            int c = kk * 2 + (lane >> 4);
            offA[kk][f] = r * 64 + (((c ^ ((r >> 1) & 3))) << 4);
        }
#pragma unroll
        for (int g = 0; g < 4; g++) {
            int r = wn * 64 + g * 16 + (lane & 7) + ((lane >> 4) << 3);
            int c = kk * 2 + ((lane >> 3) & 1);
            offB[kk][g] = r * 64 + (((c ^ ((r >> 1) & 3))) << 4);
        }
    }

    float acc[4][8][4];
#pragma unroll
    for (int f = 0; f < 4; f++)
#pragma unroll
        for (int g = 0; g < 8; g++)
#pragma unroll
            for (int j = 0; j < 4; j++) acc[f][g][j] = 0.f;

    auto load_chunk = [&](int c, int buf) {
        const int k0 = c * 32;
        const uint32_t da = buf ? sa1 : sa0;
        const uint32_t db = buf ? sb1 : sb0;
#pragma unroll
        for (int i = 0; i < 4; i++) {
            cp16(da + lsw[i], Fp + (size_t)bm * KDIM + k0 + lsrc[i]);
            cp16(db + lsw[i], Fp + (size_t)bn * KDIM + k0 + lsrc[i]);
        }
        cp_commit();
    };

    load_chunk(0, 0);

    for (int c = 0; c < NCHK; c++) {
        const int b = c & 1;
        if (c + 1 < NCHK) { load_chunk(c + 1, b ^ 1); cp_wait<1>(); }
        else cp_wait<0>();
        __syncthreads();

        const uint32_t da = b ? sa1 : sa0;
        const uint32_t db = b ? sb1 : sb0;
#pragma unroll
        for (int kk = 0; kk < 2; kk++) {
            uint32_t ra[4][4], rb[4][4];
#pragma unroll
            for (int f = 0; f < 4; f++) ldsm4(ra[f], da + offA[kk][f]);
#pragma unroll
            for (int g = 0; g < 4; g++) ldsm4(rb[g], db + offB[kk][g]);
#pragma unroll
            for (int f = 0; f < 4; f++)
#pragma unroll
                for (int g = 0; g < 4; g++) {
                    mma16816(acc[f][2 * g + 0], ra[f], rb[g][0], rb[g][1]);
                    mma16816(acc[f][2 * g + 1], ra[f], rb[g][2], rb[g][3]);
                }
        }
        __syncthreads();
    }

    const int col0 = bn + wn * 64 + (lane & 3) * 2;
#pragma unroll
    for (int f = 0; f < 4; f++) {
        const int row0 = bm + wm * 64 + f * 16 + (lane >> 2);
#pragma unroll
        for (int g = 0; g < 8; g++) {
            const int col = col0 + g * 8;
            float2 v0, v1;
            v0.x = acc[f][g][0]; v0.y = acc[f][g][1];
            v1.x = acc[f][g][2]; v1.y = acc[f][g][3];
            *(float2*)(C + (size_t)row0 * Nn + col) = v0;
            *(float2*)(C + (size_t)(row0 + 8) * Nn + col) = v1;
        }
    }

    if (bi != bj) {
#pragma unroll
        for (int cc = 0; cc < 2; cc++) {
            __syncthreads();
            float* buf = smT + wn * (32 * 128);
#pragma unroll
            for (int gl = 0; gl < 4; gl++) {
                const int g = cc * 4 + gl;
                const int cl = gl * 8 + (lane & 3) * 2;
#pragma unroll
                for (int f = 0; f < 4; f++) {
                    const int r = wm * 64 + f * 16 + (lane >> 2);
                    buf[cl * 128 + r]           = acc[f][g][0];
                    buf[(cl + 1) * 128 + r]     = acc[f][g][1];
                    buf[cl * 128 + r + 8]       = acc[f][g][2];
                    buf[(cl + 1) * 128 + r + 8] = acc[f][g][3];
                }
            }
            __syncthreads();
            for (int idx = tid; idx < 64 * 32; idx += 128) {
                const int rr = idx >> 5;
                const int sg = idx & 31;
                const int b2 = rr >> 5;
                const int cl = rr & 31;
                const int cAbs = bn + b2 * 64 + cc * 32 + cl;
                float4 v = *(float4*)(smT + b2 * (32 * 128) + cl * 128 + sg * 4);
                *(float4*)(C + (size_t)cAbs * Nn + bm + sg * 4) = v;
            }
        }
    }
}

// ---------------- fp32 -> fp16 convert ---------------------------------------
__global__ void split_kernel(const float* __restrict__ x, uint16_t* __restrict__ hi,
                             int n4)
{
    int i = blockIdx.x * blockDim.x + threadIdx.x;
    if (i >= n4) return;
    float4 v = ((const float4*)x)[i];
    ushort4 hv;
    hv.x = __half_as_ushort(__float2half_rn(v.x));
    hv.y = __half_as_ushort(__float2half_rn(v.y));
    hv.z = __half_as_ushort(__float2half_rn(v.z));
    hv.w = __half_as_ushort(__float2half_rn(v.w));
    ((ushort4*)hi)[i] = hv;
}

// ---------------- LayerNorm -> fp16 directly ---------------------------------
__global__ void ln_kernel(const float* __restrict__ g0, const float* __restrict__ be0,
                          const float* __restrict__ g1, const float* __restrict__ be1)
{
    int row = blockIdx.x;
    const float* x = g_seq + (size_t)row * Dd;
    int tid = threadIdx.x;
    float v0 = x[tid], v1 = x[tid + 256];
    __shared__ float rs[256], rq[256];
    rs[tid] = v0 + v1;
    rq[tid] = v0 * v0 + v1 * v1;
    __syncthreads();
    for (int st = 128; st > 0; st >>= 1) {
        if (tid < st) { rs[tid] += rs[tid + st]; rq[tid] += rq[tid + st]; }
        __syncthreads();
    }
    float mean = rs[0] * (1.f / Dd);
    float var = rq[0] * (1.f / Dd) - mean * mean;
    float inv = rsqrtf(var + 1e-5f);
    const float* gg = (row & 1) ? g1 : g0;
    const float* bb = (row & 1) ? be1 : be0;
    float y0 = (v0 - mean) * inv * gg[tid] + bb[tid];
    float y1 = (v1 - mean) * inv * gg[tid + 256] + bb[tid + 256];
    size_t base = (size_t)row * Dd;
    g_ah[base + tid]       = __half_as_ushort(__float2half_rn(y0));
    g_ah[base + tid + 256] = __half_as_ushort(__float2half_rn(y1));
}

// ---------------- 2-token multihead attention -> ctx fp16 --------------------
__global__ void attn_kernel()
{
    int gt = blockIdx.x * blockDim.x + threadIdx.x;
    int gw = gt >> 5, lane = gt & 31;
    if (gw >= Nn * NHEADS) return;
    int node = gw >> 3, h = gw & 7;
    const float* base = g_qkv + (size_t)node * 2 * (3 * Dd);
    int d0 = lane * 2;
    float q[2][2], k[2][2], v[2][2];
#pragma unroll
    for (int t = 0; t < 2; t++) {
        const float* r = base + t * (3 * Dd) + h * HDIM;
        float2 qq = *(const float2*)(r + d0);
        float2 kk = *(const float2*)(r + Dd + d0);
        float2 vv = *(const float2*)(r + 2 * Dd + d0);
        q[t][0] = qq.x; q[t][1] = qq.y;
        k[t][0] = kk.x; k[t][1] = kk.y;
        v[t][0] = vv.x; v[t][1] = vv.y;
    }
    float s[2][2];
#pragma unroll
    for (int qi = 0; qi < 2; qi++)
#pragma unroll
        for (int ki = 0; ki < 2; ki++)
            s[qi][ki] = q[qi][0] * k[ki][0] + q[qi][1] * k[ki][1];
#pragma unroll
    for (int o = 16; o > 0; o >>= 1)
#pragma unroll
        for (int qi = 0; qi < 2; qi++)
#pragma unroll
            for (int ki = 0; ki < 2; ki++)
                s[qi][ki] += __shfl_xor_sync(0xffffffffu, s[qi][ki], o);
    const float scale = 0.125f;
#pragma unroll
    for (int qi = 0; qi < 2; qi++) {
        float a0 = s[qi][0] * scale, a1 = s[qi][1] * scale;
        float m = fmaxf(a0, a1);
        float e0 = __expf(a0 - m), e1 = __expf(a1 - m);
        float inv = 1.f / (e0 + e1);
        float w0 = e0 * inv, w1 = e1 * inv;
        float o0 = w0 * v[0][0] + w1 * v[1][0];
        float o1 = w0 * v[0][1] + w1 * v[1][1];
        size_t off = (size_t)(node * 2 + qi) * Dd + h * HDIM + d0;
        ushort2 hv;
        hv.x = __half_as_ushort(__float2half_rn(o0));
        hv.y = __half_as_ushort(__float2half_rn(o1));
        *(ushort2*)(g_ah + off) = hv;
    }
}

// ---------------- mean over the 2 tokens -> fused fp16 -----------------------
__global__ void mean_kernel()
{
    int i = blockIdx.x * blockDim.x + threadIdx.x;
    if (i >= Nn * Dd / 4) return;
    int e0 = i * 4;
    int node = e0 / Dd, d = e0 - node * Dd;
    const float* r0 = g_att + (size_t)(node * 2) * Dd + d;
    const float* r1 = g_att + (size_t)(node * 2 + 1) * Dd + d;
    float4 a = *(const float4*)r0, b = *(const float4*)r1;
    ushort4 hv;
    hv.x = __half_as_ushort(__float2half_rn(0.5f * (a.x + b.x)));
    hv.y = __half_as_ushort(__float2half_rn(0.5f * (a.y + b.y)));
    hv.z = __half_as_ushort(__float2half_rn(0.5f * (a.z + b.z)));
    hv.w = __half_as_ushort(__float2half_rn(0.5f * (a.w + b.w)));
    ((ushort4*)g_fh)[i] = hv;
}

// ---------------- softmax stats + top-16 via segment-max hierarchy ----------
__global__ void topk_kernel(float* __restrict__ Hout)
{
    int row = blockIdx.x;
    extern __shared__ float sh[];                 // Nn floats + 256 segmax
    float* segmax = sh + Nn;
    __shared__ float swv[8];
    __shared__ int swi[8];
    __shared__ float s_bcast;
    __shared__ int s_seg;
    __shared__ float topv[TOPK];
    __shared__ int topi[TOPK];
    const float* srow = g_S + (size_t)row * Nn;
    int tid = threadIdx.x;
    int lane = tid & 31, wid = tid >> 5;

    // vectorized row load (float4)
    for (int j4 = tid; j4 < Nn / 4; j4 += 256)
        *(float4*)(sh + j4 * 4) = ((const float4*)srow)[j4];
    __syncthreads();

    {
        const int base = tid * 32;
        float sm = -INFINITY;
#pragma unroll 8
        for (int i = 0; i < 32; i++)
            sm = fmaxf(sm, sh[base + ((i + tid) & 31)]);
        segmax[tid] = sm;
        float lmax = sm;
#pragma unroll
        for (int o = 16; o > 0; o >>= 1)
            lmax = fmaxf(lmax, __shfl_xor_sync(0xffffffffu, lmax, o));
        if (lane == 0) swv[wid] = lmax;
    }
    __syncthreads();
    if (tid == 0) {
        float m = swv[0];
#pragma unroll
        for (int w = 1; w < 8; w++) m = fmaxf(m, swv[w]);
        s_bcast = m;
    }
    __syncthreads();
    const float rmax = s_bcast;

    float lsum = 0.f;
    for (int j4 = tid; j4 < Nn / 4; j4 += 256) {
        float4 v = *(float4*)(sh + j4 * 4);
        lsum += __expf(v.x - rmax) + __expf(v.y - rmax)
              + __expf(v.z - rmax) + __expf(v.w - rmax);
    }
#pragma unroll
    for (int o = 16; o > 0; o >>= 1)
        lsum += __shfl_xor_sync(0xffffffffu, lsum, o);
    if (lane == 0) swv[wid] = lsum;
    __syncthreads();
    if (tid == 0) {
        float s = 0.f;
#pragma unroll
        for (int w = 0; w < 8; w++) s += swv[w];
        s_bcast = 1.f / s;
    }
    __syncthreads();
    const float rinv = s_bcast;

    for (int kk = 0; kk < TOPK; kk++) {
        float v = segmax[tid];
        int idx = tid;
#pragma unroll
        for (int o = 16; o > 0; o >>= 1) {
            float ov = __shfl_xor_sync(0xffffffffu, v, o);
            int oi = __shfl_xor_sync(0xffffffffu, idx, o);
            if (ov > v || (ov == v && oi < idx)) { v = ov; idx = oi; }
        }
        if (lane == 0) { swv[wid] = v; swi[wid] = idx; }
        __syncthreads();
        if (tid == 0) {
            float bv = swv[0]; int bi = swi[0];
#pragma unroll
            for (int w = 1; w < 8; w++)
                if (swv[w] > bv || (swv[w] == bv && swi[w] < bi)) { bv = swv[w]; bi = swi[w]; }
            s_seg = bi;
        }
        __syncthreads();
        const int s = s_seg;
        if (wid == 0) {
            int ei = s * 32 + lane;
            float ev = sh[ei];
            float v2 = ev; int i2 = ei;
#pragma unroll
            for (int o = 16; o > 0; o >>= 1) {
                float ov = __shfl_xor_sync(0xffffffffu, v2, o);
                int oi = __shfl_xor_sync(0xffffffffu, i2, o);
                if (ov > v2 || (ov == v2 && oi < i2)) { v2 = ov; i2 = oi; }
            }
            if (lane == 0) { topv[kk] = v2; topi[kk] = i2; }
            float nv = (ei == i2) ? -INFINITY : ev;
            if (ei == i2) sh[ei] = -INFINITY;
            float mx = nv;
#pragma unroll
            for (int o = 16; o > 0; o >>= 1)
                mx = fmaxf(mx, __shfl_xor_sync(0xffffffffu, mx, o));
            if (lane == 0) segmax[s] = mx;
        }
        __syncthreads();
    }

    if (tid == 0) {
        Hout[(size_t)row * Nn + row] = 1.0f;
#pragma unroll
        for (int kk = 0; kk < TOPK; kk++)
            Hout[(size_t)topi[kk] * Nn + row] = __expf(topv[kk] - rmax) * rinv;
    }
}

__global__ void ew_kernel(const float* __restrict__ w2, const float* __restrict__ b2,
                          float* __restrict__ out)
{
    int gt = blockIdx.x * blockDim.x + threadIdx.x;
    int gw = gt >> 5, lane = gt & 31;
    if (gw >= Nn) return;
    const float* hrow = g_hidden + (size_t)gw * (Dd / 2);
    float s = 0.f;
    for (int j = lane; j < Dd / 2; j += 32) s += hrow[j] * w2[j];
#pragma unroll
    for (int o = 16; o > 0; o >>= 1) s += __shfl_xor_sync(0xffffffffu, s, o);
    if (lane == 0) {
        float v = s + b2[0];
        float sig = 1.f / (1.f + __expf(-v));
        out[gw] = fmaxf(sig, 1e-8f);
    }
}

// ---------------- launch ------------------------------------------------------
static void do_split_s(const float* src, uint16_t* hi, size_t n, cudaStream_t st)
{
    int n4 = (int)(n / 4);
    split_kernel<<<(n4 + 255) / 256, 256, 0, st>>>(src, hi, n4);
}

extern "C" void kernel_launch(void* const* d_in, const int* in_sizes, int n_in,
                              void* d_out, int out_size)
{
    const float* x0    = (const float*)d_in[0];
    const float* x1    = (const float*)d_in[1];
    const float* w_p0  = (const float*)d_in[2];
    const float* b_p0  = (const float*)d_in[3];
    const float* gg0   = (const float*)d_in[4];
    const float* be0   = (const float*)d_in[5];
    const float* w_p1  = (const float*)d_in[6];
    const float* b_p1  = (const float*)d_in[7];
    const float* gg1   = (const float*)d_in[8];
    const float* be1   = (const float*)d_in[9];
    const float* in_w  = (const float*)d_in[10];
    const float* in_b  = (const float*)d_in[11];
    const float* out_w = (const float*)d_in[12];
    const float* out_b = (const float*)d_in[13];
    const float* ew_w1 = (const float*)d_in[14];
    const float* ew_b1 = (const float*)d_in[15];
    const float* ew_w2 = (const float*)d_in[16];
    const float* ew_b2 = (const float*)d_in[17];

    float* H  = (float*)d_out;
    float* ew = H + (size_t)Nn * Nn;

    float *seq, *qkv, *att, *S, *hidden;
    uint16_t *ah, *a1h, *fh;
    uint16_t *wp0h, *wp1h, *wqh, *woh, *weh;
    cudaGetSymbolAddress((void**)&seq, g_seq);
    cudaGetSymbolAddress((void**)&qkv, g_qkv);
    cudaGetSymbolAddress((void**)&att, g_att);
    cudaGetSymbolAddress((void**)&S, g_S);
    cudaGetSymbolAddress((void**)&hidden, g_hidden);
    cudaGetSymbolAddress((void**)&ah, g_ah);
    cudaGetSymbolAddress((void**)&a1h, g_a1h);
    cudaGetSymbolAddress((void**)&wp0h, g_wp0h);
    cudaGetSymbolAddress((void**)&wp1h, g_wp1h);
    cudaGetSymbolAddress((void**)&wqh, g_wqh);
    cudaGetSymbolAddress((void**)&woh, g_woh);
    cudaGetSymbolAddress((void**)&weh, g_weh);
    cudaGetSymbolAddress((void**)&fh, g_fh);

    static cudaStream_t s1 = nullptr, s2 = nullptr;
    static cudaEvent_t eF = nullptr, eS2 = nullptr, eP1 = nullptr, eM = nullptr, eE = nullptr;
    if (!s1) {
        cudaStreamCreateWithFlags(&s1, cudaStreamNonBlocking);
        cudaStreamCreateWithFlags(&s2, cudaStreamNonBlocking);
        cudaEventCreateWithFlags(&eF,  cudaEventDisableTiming);
        cudaEventCreateWithFlags(&eS2, cudaEventDisableTiming);
        cudaEventCreateWithFlags(&eP1, cudaEventDisableTiming);
        cudaEventCreateWithFlags(&eM,  cudaEventDisableTiming);
        cudaEventCreateWithFlags(&eE,  cudaEventDisableTiming);
    }

    // fork from capture (default) stream
    cudaEventRecord(eF, 0);
    cudaStreamWaitEvent(s1, eF, 0);
    cudaStreamWaitEvent(s2, eF, 0);

    // s2: H memset + weight converts (input-only)
    cudaMemsetAsync(H, 0, (size_t)Nn * Nn * sizeof(float), s2);
    do_split_s(in_w,  wqh, (size_t)3 * Dd * Dd, s2);
    do_split_s(out_w, woh, (size_t)Dd * Dd, s2);
    do_split_s(ew_w1, weh, (size_t)(Dd / 2) * Dd, s2);
    cudaEventRecord(eS2, s2);

    // s1: modality-1 projection chain
    do_split_s(x1,   a1h,  (size_t)Nn * Dd, s1);
    do_split_s(w_p1, wp1h, (size_t)Dd * Dd, s1);
    tgemm<1, 1><<<dim3(Dd / 128, Nn / 128), 128, 0, s1>>>(a1h, wp1h, b_p1, seq + Dd, 2 * Dd);
    cudaEventRecord(eP1, s1);

    // stream 0: modality-0 projection chain
    do_split_s(x0,   ah,   (size_t)Nn * Dd, 0);
    do_split_s(w_p0, wp0h, (size_t)Dd * Dd, 0);
    tgemm<1, 1><<<dim3(Dd / 128, Nn / 128), 128>>>(ah, wp0h, b_p0, seq, 2 * Dd);

    // join proj1 + weight converts, trunk on stream 0
    cudaStreamWaitEvent(0, eP1, 0);
    ln_kernel<<<2 * Nn, 256>>>(gg0, be0, gg1, be1);
    cudaStreamWaitEvent(0, eS2, 0);
    tgemm<0, 1><<<dim3(3 * Dd / 128, 2 * Nn / 128), 128>>>(ah, wqh, in_b, qkv, 3 * Dd);
    attn_kernel<<<(Nn * NHEADS * 32) / 256, 256>>>();
    tgemm<0, 1><<<dim3(Dd / 128, 2 * Nn / 128), 128>>>(ah, woh, out_b, att, Dd);
    mean_kernel<<<(Nn * Dd / 4 + 255) / 256, 256>>>();
    cudaEventRecord(eM, 0);

    // s1: edge-weight MLP (parallel to sim GEMM + topk)
    cudaStreamWaitEvent(s1, eM, 0);
    tgemm<1, 1><<<dim3((Dd / 2) / 128, Nn / 128), 128, 0, s1>>>(fh, weh, ew_b1, hidden, Dd / 2);
    ew_kernel<<<(Nn * 32) / 256, 256, 0, s1>>>(ew_w2, ew_b2, ew);
    cudaEventRecord(eE, s1);

    // stream 0: similarity GEMM (symmetric, single kernel) + topk
    tgemm_sym<<<(Nn / 128) * (Nn / 128 + 1) / 2, 128>>>(fh, S);
    topk_kernel<<<Nn, 256, (Nn + 256) * sizeof(float)>>>(H);

    // join ew branch back into capture stream
    cudaStreamWaitEvent(0, eE, 0);
}

// round 15
// speedup vs baseline: 1.5514x; 1.0089x over previous
#include <cuda_runtime.h>
#include <cuda_fp16.h>
#include <math.h>
#include <stdint.h>

#define Nn 8192
#define Dd 512
#define KDIM 512
#define NHEADS 8
#define HDIM 64
#define TOPK 16

// ---------------- scratch (static device globals; no allocation) -------------
__device__ uint16_t g_seqh[2 * Nn * Dd];        // proj+bias+relu out (fp16)
__device__ uint16_t g_qkvh[2 * Nn * 3 * Dd];    // qkv out (fp16)
__device__ uint16_t g_atth[2 * Nn * Dd];        // out-proj out (fp16)
__device__ float g_S[(size_t)Nn * Nn];
__device__ float g_hidden[Nn * (Dd / 2)];
__device__ uint16_t g_ah[2 * Nn * Dd];          // activations (fp16)
__device__ uint16_t g_a1h[Nn * Dd];             // proj1 act
__device__ uint16_t g_wp0h[Dd * Dd];
__device__ uint16_t g_wp1h[Dd * Dd];
__device__ uint16_t g_wqh[3 * Dd * Dd];
__device__ uint16_t g_woh[Dd * Dd];
__device__ uint16_t g_weh[(Dd / 2) * Dd];
__device__ uint16_t g_fh[Nn * Dd];              // fused (fp16)

// ============================ PTX helpers ====================================
__device__ __forceinline__ uint32_t smem_u32(const void* p) {
    uint32_t a;
    asm("{ .reg .u64 t; cvta.to.shared.u64 t, %1; cvt.u32.u64 %0, t; }" : "=r"(a) : "l"(p));
    return a;
}
__device__ __forceinline__ void cp16(uint32_t dst, const void* src) {
    asm volatile("cp.async.cg.shared.global [%0], [%1], 16;" :: "r"(dst), "l"(src) : "memory");
}
__device__ __forceinline__ void cp_commit() {
    asm volatile("cp.async.commit_group;" ::: "memory");
}
template <int N> __device__ __forceinline__ void cp_wait() {
    asm volatile("cp.async.wait_group %0;" :: "n"(N) : "memory");
}
__device__ __forceinline__ void ldsm4(uint32_t* r, uint32_t a) {
    asm volatile("ldmatrix.sync.aligned.m8n8.x4.shared.b16 {%0,%1,%2,%3}, [%4];"
                 : "=r"(r[0]), "=r"(r[1]), "=r"(r[2]), "=r"(r[3]) : "r"(a));
}
__device__ __forceinline__ void mma16816(float* c, const uint32_t* a, uint32_t b0, uint32_t b1) {
    asm volatile("mma.sync.aligned.m16n8k16.row.col.f32.f16.f16.f32 "
                 "{%0,%1,%2,%3}, {%4,%5,%6,%7}, {%8,%9}, {%0,%1,%2,%3};"
                 : "+f"(c[0]), "+f"(c[1]), "+f"(c[2]), "+f"(c[3])
                 : "r"(a[0]), "r"(a[1]), "r"(a[2]), "r"(a[3]), "r"(b0), "r"(b1));
}

// ======================= warp-MMA NT GEMM (fp16, fp32 acc) ===================
// HALF_OUT: write C as fp16 (__half2), else fp32 (float2).
template <int RELU, int HAS_BIAS, int HALF_OUT>
__global__ __launch_bounds__(128, 2) void tgemm(
    const uint16_t* __restrict__ Ap, const uint16_t* __restrict__ Bp,
    const float* __restrict__ bias, void* __restrict__ Cv, int ldc)
{
    __shared__ uint16_t sA[2][128 * 32];
    __shared__ uint16_t sB[2][128 * 32];

    const int tid = threadIdx.x;
    const int lane = tid & 31, wid = tid >> 5;
    const int wm = wid & 1;
    const int wn = wid >> 1;
    const int bm = blockIdx.y * 128, bn = blockIdx.x * 128;

    const uint32_t sa0 = smem_u32(&sA[0][0]), sa1 = smem_u32(&sA[1][0]);
    const uint32_t sb0 = smem_u32(&sB[0][0]), sb1 = smem_u32(&sB[1][0]);

    const int NCHK = KDIM / 32;

    uint32_t lsw[4]; size_t lsrc[4];
#pragma unroll
    for (int i = 0; i < 4; i++) {
        int s = tid + 128 * i;
        int r = s >> 2, c = s & 3;
        lsw[i] = r * 64 + (((c ^ ((r >> 1) & 3))) << 4);
        lsrc[i] = (size_t)r * KDIM + c * 8;
    }

    uint32_t offA[2][4], offB[2][4];
#pragma unroll
    for (int kk = 0; kk < 2; kk++) {
#pragma unroll
        for (int f = 0; f < 4; f++) {
            int r = wm * 64 + f * 16 + (lane & 15);
            int c = kk * 2 + (lane >> 4);
            offA[kk][f] = r * 64 + (((c ^ ((r >> 1) & 3))) << 4);
        }
#pragma unroll
        for (int g = 0; g < 4; g++) {
            int r = wn * 64 + g * 16 + (lane & 7) + ((lane >> 4) << 3);
            int c = kk * 2 + ((lane >> 3) & 1);
            offB[kk][g] = r * 64 + (((c ^ ((r >> 1) & 3))) << 4);
        }
    }

    float acc[4][8][4];
#pragma unroll
    for (int f = 0; f < 4; f++)
#pragma unroll
        for (int g = 0; g < 8; g++)
#pragma unroll
            for (int j = 0; j < 4; j++) acc[f][g][j] = 0.f;

    auto load_chunk = [&](int c, int buf) {
        const int k0 = c * 32;
        const uint32_t da = buf ? sa1 : sa0;
        const uint32_t db = buf ? sb1 : sb0;
#pragma unroll
        for (int i = 0; i < 4; i++) {
            cp16(da + lsw[i], Ap + (size_t)bm * KDIM + k0 + lsrc[i]);
            cp16(db + lsw[i], Bp + (size_t)bn * KDIM + k0 + lsrc[i]);
        }
        cp_commit();
    };

    load_chunk(0, 0);

    for (int c = 0; c < NCHK; c++) {
        const int b = c & 1;
        if (c + 1 < NCHK) { load_chunk(c + 1, b ^ 1); cp_wait<1>(); }
        else cp_wait<0>();
        __syncthreads();

        const uint32_t da = b ? sa1 : sa0;
        const uint32_t db = b ? sb1 : sb0;
#pragma unroll
        for (int kk = 0; kk < 2; kk++) {
            uint32_t ra[4][4], rb[4][4];
#pragma unroll
            for (int f = 0; f < 4; f++) ldsm4(ra[f], da + offA[kk][f]);
#pragma unroll
            for (int g = 0; g < 4; g++) ldsm4(rb[g], db + offB[kk][g]);
#pragma unroll
            for (int f = 0; f < 4; f++)
#pragma unroll
                for (int g = 0; g < 4; g++) {
                    mma16816(acc[f][2 * g + 0], ra[f], rb[g][0], rb[g][1]);
                    mma16816(acc[f][2 * g + 1], ra[f], rb[g][2], rb[g][3]);
                }
        }
        __syncthreads();
    }

    const int col0 = bn + wn * 64 + (lane & 3) * 2;
#pragma unroll
    for (int f = 0; f < 4; f++) {
        const int row0 = bm + wm * 64 + f * 16 + (lane >> 2);
#pragma unroll
        for (int g = 0; g < 8; g++) {
            const int col = col0 + g * 8;
            float b0 = 0.f, b1 = 0.f;
            if (HAS_BIAS) { b0 = bias[col]; b1 = bias[col + 1]; }
            float2 v0, v1;
            v0.x = acc[f][g][0] + b0; v0.y = acc[f][g][1] + b1;
            v1.x = acc[f][g][2] + b0; v1.y = acc[f][g][3] + b1;
            if (RELU) {
                v0.x = fmaxf(v0.x, 0.f); v0.y = fmaxf(v0.y, 0.f);
                v1.x = fmaxf(v1.x, 0.f); v1.y = fmaxf(v1.y, 0.f);
            }
            if (HALF_OUT) {
                uint16_t* Ch = (uint16_t*)Cv;
                *(__half2*)(Ch + (size_t)row0 * ldc + col) = __floats2half2_rn(v0.x, v0.y);
                *(__half2*)(Ch + (size_t)(row0 + 8) * ldc + col) = __floats2half2_rn(v1.x, v1.y);
            } else {
                float* Cf = (float*)Cv;
                *(float2*)(Cf + (size_t)row0 * ldc + col) = v0;
                *(float2*)(Cf + (size_t)(row0 + 8) * ldc + col) = v1;
            }
        }
    }
}

// ============== symmetric variant: S = F*F^T, upper-triangle blocks ==========
__global__ __launch_bounds__(128, 2) void tgemm_sym(
    const uint16_t* __restrict__ Fp, float* __restrict__ C)
{
    __shared__ __align__(16) uint8_t smraw[32768];
    float* smT = (float*)smraw;

    const int tid = threadIdx.x;
    const int lane = tid & 31, wid = tid >> 5;
    const int wm = wid & 1;
    const int wn = wid >> 1;

    int t = blockIdx.x;
    int bj = (int)((sqrtf(8.f * t + 1.f) - 1.f) * 0.5f);
    while ((bj + 1) * (bj + 2) / 2 <= t) bj++;
    while (bj * (bj + 1) / 2 > t) bj--;
    int bi = t - bj * (bj + 1) / 2;
    const int bm = bi * 128, bn = bj * 128;

    const uint32_t sa0 = smem_u32(smraw), sa1 = smem_u32(smraw + 8192);
    const uint32_t sb0 = smem_u32(smraw + 16384), sb1 = smem_u32(smraw + 24576);

    const int NCHK = KDIM / 32;

    uint32_t lsw[4]; size_t lsrc[4];
#pragma unroll
    for (int i = 0; i < 4; i++) {
        int s = tid + 128 * i;
        int r = s >> 2, c = s & 3;
        lsw[i] = r * 64 + (((c ^ ((r >> 1) & 3))) << 4);
        lsrc[i] = (size_t)r * KDIM + c * 8;
    }

    uint32_t offA[2][4], offB[2][4];
#pragma unroll
    for (int kk = 0; kk < 2; kk++) {
#pragma unroll
        for (int f = 0; f < 4; f++) {
            int r = wm * 64 + f * 16 + (lane & 15);
            int c = kk * 2 + (lane >> 4);
            offA[kk][f] = r * 64 + (((c ^ ((r >> 1) & 3))) << 4);
        }
#pragma unroll
        for (int g = 0; g < 4; g++) {
            int r = wn * 64 + g * 16 + (lane & 7) + ((lane >> 4) << 3);
            int c = kk * 2 + ((lane >> 3) & 1);
            offB[kk][g] = r * 64 + (((c ^ ((r >> 1) & 3))) << 4);
        }
    }

    float acc[4][8][4];
#pragma unroll
    for (int f = 0; f < 4; f++)
#pragma unroll
        for (int g = 0; g < 8; g++)
#pragma unroll
            for (int j = 0; j < 4; j++) acc[f][g][j] = 0.f;

    auto load_chunk = [&](int c, int buf) {
        const int k0 = c * 32;
        const uint32_t da = buf ? sa1 : sa0;
        const uint32_t db = buf ? sb1 : sb0;
#pragma unroll
        for (int i = 0; i < 4; i++) {
            cp16(da + lsw[i], Fp + (size_t)bm * KDIM + k0 + lsrc[i]);
            cp16(db + lsw[i], Fp + (size_t)bn * KDIM + k0 + lsrc[i]);
        }
        cp_commit();
    };

    load_chunk(0, 0);

    for (int c = 0; c < NCHK; c++) {
        const int b = c & 1;
        if (c + 1 < NCHK) { load_chunk(c + 1, b ^ 1); cp_wait<1>(); }
        else cp_wait<0>();
        __syncthreads();

        const uint32_t da = b ? sa1 : sa0;
        const uint32_t db = b ? sb1 : sb0;
#pragma unroll
        for (int kk = 0; kk < 2; kk++) {
            uint32_t ra[4][4], rb[4][4];
#pragma unroll
            for (int f = 0; f < 4; f++) ldsm4(ra[f], da + offA[kk][f]);
#pragma unroll
            for (int g = 0; g < 4; g++) ldsm4(rb[g], db + offB[kk][g]);
#pragma unroll
            for (int f = 0; f < 4; f++)
#pragma unroll
                for (int g = 0; g < 4; g++) {
                    mma16816(acc[f][2 * g + 0], ra[f], rb[g][0], rb[g][1]);
                    mma16816(acc[f][2 * g + 1], ra[f], rb[g][2], rb[g][3]);
                }
        }
        __syncthreads();
    }

    const int col0 = bn + wn * 64 + (lane & 3) * 2;
#pragma unroll
    for (int f = 0; f < 4; f++) {
        const int row0 = bm + wm * 64 + f * 16 + (lane >> 2);
#pragma unroll
        for (int g = 0; g < 8; g++) {
            const int col = col0 + g * 8;
            float2 v0, v1;
            v0.x = acc[f][g][0]; v0.y = acc[f][g][1];
            v1.x = acc[f][g][2]; v1.y = acc[f][g][3];
            *(float2*)(C + (size_t)row0 * Nn + col) = v0;
            *(float2*)(C + (size_t)(row0 + 8) * Nn + col) = v1;
        }
    }

    if (bi != bj) {
#pragma unroll
        for (int cc = 0; cc < 2; cc++) {
            __syncthreads();
            float* buf = smT + wn * (32 * 128);
#pragma unroll
            for (int gl = 0; gl < 4; gl++) {
                const int g = cc * 4 + gl;
                const int cl = gl * 8 + (lane & 3) * 2;
#pragma unroll
                for (int f = 0; f < 4; f++) {
                    const int r = wm * 64 + f * 16 + (lane >> 2);
                    buf[cl * 128 + r]           = acc[f][g][0];
                    buf[(cl + 1) * 128 + r]     = acc[f][g][1];
                    buf[cl * 128 + r + 8]       = acc[f][g][2];
                    buf[(cl + 1) * 128 + r + 8] = acc[f][g][3];
                }
            }
            __syncthreads();
            for (int idx = tid; idx < 64 * 32; idx += 128) {
                const int rr = idx >> 5;
                const int sg = idx & 31;
                const int b2 = rr >> 5;
                const int cl = rr & 31;
                const int cAbs = bn + b2 * 64 + cc * 32 + cl;
                float4 v = *(float4*)(smT + b2 * (32 * 128) + cl * 128 + sg * 4);
                *(float4*)(C + (size_t)cAbs * Nn + bm + sg * 4) = v;
            }
        }
    }
}

// ---------------- fp32 -> fp16 convert ---------------------------------------
__global__ void split_kernel(const float* __restrict__ x, uint16_t* __restrict__ hi,
                             int n4)
{
    int i = blockIdx.x * blockDim.x + threadIdx.x;
    if (i >= n4) return;
    float4 v = ((const float4*)x)[i];
    ushort4 hv;
    hv.x = __half_as_ushort(__float2half_rn(v.x));
    hv.y = __half_as_ushort(__float2half_rn(v.y));
    hv.z = __half_as_ushort(__float2half_rn(v.z));
    hv.w = __half_as_ushort(__float2half_rn(v.w));
    ((ushort4*)hi)[i] = hv;
}

// ---------------- LayerNorm (fp16 in) -> fp16 act ----------------------------
__global__ void ln_kernel(const float* __restrict__ g0, const float* __restrict__ be0,
                          const float* __restrict__ g1, const float* __restrict__ be1)
{
    int row = blockIdx.x;
    const uint16_t* x = g_seqh + (size_t)row * Dd;
    int tid = threadIdx.x;
    float v0 = __half2float(__ushort_as_half(x[tid]));
    float v1 = __half2float(__ushort_as_half(x[tid + 256]));
    __shared__ float rs[256], rq[256];
    rs[tid] = v0 + v1;
    rq[tid] = v0 * v0 + v1 * v1;
    __syncthreads();
    for (int st = 128; st > 0; st >>= 1) {
        if (tid < st) { rs[tid] += rs[tid + st]; rq[tid] += rq[tid + st]; }
        __syncthreads();
    }
    float mean = rs[0] * (1.f / Dd);
    float var = rq[0] * (1.f / Dd) - mean * mean;
    float inv = rsqrtf(var + 1e-5f);
    const float* gg = (row & 1) ? g1 : g0;
    const float* bb = (row & 1) ? be1 : be0;
    float y0 = (v0 - mean) * inv * gg[tid] + bb[tid];
    float y1 = (v1 - mean) * inv * gg[tid + 256] + bb[tid + 256];
    size_t base = (size_t)row * Dd;
    g_ah[base + tid]       = __half_as_ushort(__float2half_rn(y0));
    g_ah[base + tid + 256] = __half_as_ushort(__float2half_rn(y1));
}

// ---------------- 2-token multihead attention (fp16 qkv) -> ctx fp16 ---------
__global__ void attn_kernel()
{
    int gt = blockIdx.x * blockDim.x + threadIdx.x;
    int gw = gt >> 5, lane = gt & 31;
    if (gw >= Nn * NHEADS) return;
    int node = gw >> 3, h = gw & 7;
    const uint16_t* base = g_qkvh + (size_t)node * 2 * (3 * Dd);
    int d0 = lane * 2;
    float q[2][2], k[2][2], v[2][2];
#pragma unroll
    for (int t = 0; t < 2; t++) {
        const uint16_t* r = base + t * (3 * Dd) + h * HDIM;
        float2 qq = __half22float2(*(const __half2*)(r + d0));
        float2 kk = __half22float2(*(const __half2*)(r + Dd + d0));
        float2 vv = __half22float2(*(const __half2*)(r + 2 * Dd + d0));
        q[t][0] = qq.x; q[t][1] = qq.y;
        k[t][0] = kk.x; k[t][1] = kk.y;
        v[t][0] = vv.x; v[t][1] = vv.y;
    }
    float s[2][2];
#pragma unroll
    for (int qi = 0; qi < 2; qi++)
#pragma unroll
        for (int ki = 0; ki < 2; ki++)
            s[qi][ki] = q[qi][0] * k[ki][0] + q[qi][1] * k[ki][1];
#pragma unroll
    for (int o = 16; o > 0; o >>= 1)
#pragma unroll
        for (int qi = 0; qi < 2; qi++)
#pragma unroll
            for (int ki = 0; ki < 2; ki++)
                s[qi][ki] += __shfl_xor_sync(0xffffffffu, s[qi][ki], o);
    const float scale = 0.125f;
#pragma unroll
    for (int qi = 0; qi < 2; qi++) {
        float a0 = s[qi][0] * scale, a1 = s[qi][1] * scale;
        float m = fmaxf(a0, a1);
        float e0 = __expf(a0 - m), e1 = __expf(a1 - m);
        float inv = 1.f / (e0 + e1);
        float w0 = e0 * inv, w1 = e1 * inv;
        float o0 = w0 * v[0][0] + w1 * v[1][0];
        float o1 = w0 * v[0][1] + w1 * v[1][1];
        size_t off = (size_t)(node * 2 + qi) * Dd + h * HDIM + d0;
        *(__half2*)(g_ah + off) = __floats2half2_rn(o0, o1);
    }
}

// ---------------- mean over the 2 tokens (fp16 in) -> fused fp16 -------------
__global__ void mean_kernel()
{
    int i = blockIdx.x * blockDim.x + threadIdx.x;   // half2-pair index (4 elems)
    if (i >= Nn * Dd / 4) return;
    int e0 = i * 4;
    int node = e0 / Dd, d = e0 - node * Dd;
    const uint16_t* r0 = g_atth + (size_t)(node * 2) * Dd + d;
    const uint16_t* r1 = g_atth + (size_t)(node * 2 + 1) * Dd + d;
    __half2 a0 = *(const __half2*)(r0);
    __half2 a1 = *(const __half2*)(r0 + 2);
    __half2 b0 = *(const __half2*)(r1);
    __half2 b1 = *(const __half2*)(r1 + 2);
    float2 fa0 = __half22float2(a0), fa1 = __half22float2(a1);
    float2 fb0 = __half22float2(b0), fb1 = __half22float2(b1);
    __half2 h0 = __floats2half2_rn(0.5f * (fa0.x + fb0.x), 0.5f * (fa0.y + fb0.y));
    __half2 h1 = __floats2half2_rn(0.5f * (fa1.x + fb1.x), 0.5f * (fa1.y + fb1.y));
    *(__half2*)(g_fh + (size_t)e0 / 4 * 4)     = h0;
    *(__half2*)(g_fh + (size_t)e0 / 4 * 4 + 2) = h1;
}

// ---------------- softmax stats + top-16 via segment-max hierarchy ----------
__global__ void topk_kernel(float* __restrict__ Hout)
{
    int row = blockIdx.x;
    extern __shared__ float sh[];                 // Nn floats + 256 segmax
    float* segmax = sh + Nn;
    __shared__ float swv[8];
    __shared__ int swi[8];
    __shared__ float s_bcast;
    __shared__ int s_seg;
    __shared__ float topv[TOPK];
    __shared__ int topi[TOPK];
    const float* srow = g_S + (size_t)row * Nn;
    int tid = threadIdx.x;
    int lane = tid & 31, wid = tid >> 5;

    for (int j4 = tid; j4 < Nn / 4; j4 += 256)
        *(float4*)(sh + j4 * 4) = ((const float4*)srow)[j4];
    __syncthreads();

    {
        const int base = tid * 32;
        float sm = -INFINITY;
#pragma unroll 8
        for (int i = 0; i < 32; i++)
            sm = fmaxf(sm, sh[base + ((i + tid) & 31)]);
        segmax[tid] = sm;
        float lmax = sm;
#pragma unroll
        for (int o = 16; o > 0; o >>= 1)
            lmax = fmaxf(lmax, __shfl_xor_sync(0xffffffffu, lmax, o));
        if (lane == 0) swv[wid] = lmax;
    }
    __syncthreads();
    if (tid == 0) {
        float m = swv[0];
#pragma unroll
        for (int w = 1; w < 8; w++) m = fmaxf(m, swv[w]);
        s_bcast = m;
    }
    __syncthreads();
    const float rmax = s_bcast;

    float lsum = 0.f;
    for (int j4 = tid; j4 < Nn / 4; j4 += 256) {
        float4 v = *(float4*)(sh + j4 * 4);
        lsum += __expf(v.x - rmax) + __expf(v.y - rmax)
              + __expf(v.z - rmax) + __expf(v.w - rmax);
    }
#pragma unroll
    for (int o = 16; o > 0; o >>= 1)
        lsum += __shfl_xor_sync(0xffffffffu, lsum, o);
    if (lane == 0) swv[wid] = lsum;
    __syncthreads();
    if (tid == 0) {
        float s = 0.f;
#pragma unroll
        for (int w = 0; w < 8; w++) s += swv[w];
        s_bcast = 1.f / s;
    }
    __syncthreads();
    const float rinv = s_bcast;

    for (int kk = 0; kk < TOPK; kk++) {
        float v = segmax[tid];
        int idx = tid;
#pragma unroll
        for (int o = 16; o > 0; o >>= 1) {
            float ov = __shfl_xor_sync(0xffffffffu, v, o);
            int oi = __shfl_xor_sync(0xffffffffu, idx, o);
            if (ov > v || (ov == v && oi < idx)) { v = ov; idx = oi; }
        }
        if (lane == 0) { swv[wid] = v; swi[wid] = idx; }
        __syncthreads();
        if (tid == 0) {
            float bv = swv[0]; int bi = swi[0];
#pragma unroll
            for (int w = 1; w < 8; w++)
                if (swv[w] > bv || (swv[w] == bv && swi[w] < bi)) { bv = swv[w]; bi = swi[w]; }
            s_seg = bi;
        }
        __syncthreads();
        const int s = s_seg;
        if (wid == 0) {
            int ei = s * 32 + lane;
            float ev = sh[ei];
            float v2 = ev; int i2 = ei;
#pragma unroll
            for (int o = 16; o > 0; o >>= 1) {
                float ov = __shfl_xor_sync(0xffffffffu, v2, o);
                int oi = __shfl_xor_sync(0xffffffffu, i2, o);
                if (ov > v2 || (ov == v2 && oi < i2)) { v2 = ov; i2 = oi; }
            }
            if (lane == 0) { topv[kk] = v2; topi[kk] = i2; }
            float nv = (ei == i2) ? -INFINITY : ev;
            if (ei == i2) sh[ei] = -INFINITY;
            float mx = nv;
#pragma unroll
            for (int o = 16; o > 0; o >>= 1)
                mx = fmaxf(mx, __shfl_xor_sync(0xffffffffu, mx, o));
            if (lane == 0) segmax[s] = mx;
        }
        __syncthreads();
    }

    if (tid == 0) {
        Hout[(size_t)row * Nn + row] = 1.0f;
#pragma unroll
        for (int kk = 0; kk < TOPK; kk++)
            Hout[(size_t)topi[kk] * Nn + row] = __expf(topv[kk] - rmax) * rinv;
    }
}

__global__ void ew_kernel(const float* __restrict__ w2, const float* __restrict__ b2,
                          float* __restrict__ out)
{
    int gt = blockIdx.x * blockDim.x + threadIdx.x;
    int gw = gt >> 5, lane = gt & 31;
    if (gw >= Nn) return;
    const float* hrow = g_hidden + (size_t)gw * (Dd / 2);
    float s = 0.f;
    for (int j = lane; j < Dd / 2; j += 32) s += hrow[j] * w2[j];
#pragma unroll
    for (int o = 16; o > 0; o >>= 1) s += __shfl_xor_sync(0xffffffffu, s, o);
    if (lane == 0) {
        float v = s + b2[0];
        float sig = 1.f / (1.f + __expf(-v));
        out[gw] = fmaxf(sig, 1e-8f);
    }
}

// ---------------- launch ------------------------------------------------------
static void do_split_s(const float* src, uint16_t* hi, size_t n, cudaStream_t st)
{
    int n4 = (int)(n / 4);
    split_kernel<<<(n4 + 255) / 256, 256, 0, st>>>(src, hi, n4);
}

extern "C" void kernel_launch(void* const* d_in, const int* in_sizes, int n_in,
                              void* d_out, int out_size)
{
    const float* x0    = (const float*)d_in[0];
    const float* x1    = (const float*)d_in[1];
    const float* w_p0  = (const float*)d_in[2];
    const float* b_p0  = (const float*)d_in[3];
    const float* gg0   = (const float*)d_in[4];
    const float* be0   = (const float*)d_in[5];
    const float* w_p1  = (const float*)d_in[6];
    const float* b_p1  = (const float*)d_in[7];
    const float* gg1   = (const float*)d_in[8];
    const float* be1   = (const float*)d_in[9];
    const float* in_w  = (const float*)d_in[10];
    const float* in_b  = (const float*)d_in[11];
    const float* out_w = (const float*)d_in[12];
    const float* out_b = (const float*)d_in[13];
    const float* ew_w1 = (const float*)d_in[14];
    const float* ew_b1 = (const float*)d_in[15];
    const float* ew_w2 = (const float*)d_in[16];
    const float* ew_b2 = (const float*)d_in[17];

    float* H  = (float*)d_out;
    float* ew = H + (size_t)Nn * Nn;

    float *S, *hidden;
    uint16_t *seqh, *qkvh, *atth;
    uint16_t *ah, *a1h, *fh;
    uint16_t *wp0h, *wp1h, *wqh, *woh, *weh;
    cudaGetSymbolAddress((void**)&seqh, g_seqh);
    cudaGetSymbolAddress((void**)&qkvh, g_qkvh);
    cudaGetSymbolAddress((void**)&atth, g_atth);
    cudaGetSymbolAddress((void**)&S, g_S);
    cudaGetSymbolAddress((void**)&hidden, g_hidden);
    cudaGetSymbolAddress((void**)&ah, g_ah);
    cudaGetSymbolAddress((void**)&a1h, g_a1h);
    cudaGetSymbolAddress((void**)&wp0h, g_wp0h);
    cudaGetSymbolAddress((void**)&wp1h, g_wp1h);
    cudaGetSymbolAddress((void**)&wqh, g_wqh);
    cudaGetSymbolAddress((void**)&woh, g_woh);
    cudaGetSymbolAddress((void**)&weh, g_weh);
    cudaGetSymbolAddress((void**)&fh, g_fh);

    static cudaStream_t s1 = nullptr, s2 = nullptr;
    static cudaEvent_t eF = nullptr, eS2 = nullptr, eP1 = nullptr, eM = nullptr, eE = nullptr;
    if (!s1) {
        cudaStreamCreateWithFlags(&s1, cudaStreamNonBlocking);
        cudaStreamCreateWithFlags(&s2, cudaStreamNonBlocking);
        cudaEventCreateWithFlags(&eF,  cudaEventDisableTiming);
        cudaEventCreateWithFlags(&eS2, cudaEventDisableTiming);
        cudaEventCreateWithFlags(&eP1, cudaEventDisableTiming);
        cudaEventCreateWithFlags(&eM,  cudaEventDisableTiming);
        cudaEventCreateWithFlags(&eE,  cudaEventDisableTiming);
    }

    // fork from capture (default) stream
    cudaEventRecord(eF, 0);
    cudaStreamWaitEvent(s1, eF, 0);
    cudaStreamWaitEvent(s2, eF, 0);

    // s2: H memset + weight converts (input-only)
    cudaMemsetAsync(H, 0, (size_t)Nn * Nn * sizeof(float), s2);
    do_split_s(in_w,  wqh, (size_t)3 * Dd * Dd, s2);
    do_split_s(out_w, woh, (size_t)Dd * Dd, s2);
    do_split_s(ew_w1, weh, (size_t)(Dd / 2) * Dd, s2);
    cudaEventRecord(eS2, s2);

    // s1: modality-1 projection chain (fp16 out into interleaved seqh)
    do_split_s(x1,   a1h,  (size_t)Nn * Dd, s1);
    do_split_s(w_p1, wp1h, (size_t)Dd * Dd, s1);
    tgemm<1, 1, 1><<<dim3(Dd / 128, Nn / 128), 128, 0, s1>>>(a1h, wp1h, b_p1, seqh + Dd, 2 * Dd);
    cudaEventRecord(eP1, s1);

    // stream 0: modality-0 projection chain
    do_split_s(x0,   ah,   (size_t)Nn * Dd, 0);
    do_split_s(w_p0, wp0h, (size_t)Dd * Dd, 0);
    tgemm<1, 1, 1><<<dim3(Dd / 128, Nn / 128), 128>>>(ah, wp0h, b_p0, seqh, 2 * Dd);

    // join proj1 + weight converts, trunk on stream 0
    cudaStreamWaitEvent(0, eP1, 0);
    ln_kernel<<<2 * Nn, 256>>>(gg0, be0, gg1, be1);
    cudaStreamWaitEvent(0, eS2, 0);
    tgemm<0, 1, 1><<<dim3(3 * Dd / 128, 2 * Nn / 128), 128>>>(ah, wqh, in_b, qkvh, 3 * Dd);
    attn_kernel<<<(Nn * NHEADS * 32) / 256, 256>>>();
    tgemm<0, 1, 1><<<dim3(Dd / 128, 2 * Nn / 128), 128>>>(ah, woh, out_b, atth, Dd);
    mean_kernel<<<(Nn * Dd / 4 + 255) / 256, 256>>>();
    cudaEventRecord(eM, 0);

    // s1: edge-weight MLP (parallel to sim GEMM + topk)
    cudaStreamWaitEvent(s1, eM, 0);
    tgemm<1, 1, 0><<<dim3((Dd / 2) / 128, Nn / 128), 128, 0, s1>>>(fh, weh, ew_b1, hidden, Dd / 2);
    ew_kernel<<<(Nn * 32) / 256, 256, 0, s1>>>(ew_w2, ew_b2, ew);
    cudaEventRecord(eE, s1);

    // stream 0: similarity GEMM (symmetric) + topk
    tgemm_sym<<<(Nn / 128) * (Nn / 128 + 1) / 2, 128>>>(fh, S);
    topk_kernel<<<Nn, 256, (Nn + 256) * sizeof(float)>>>(H);

    // join ew branch back into capture stream
    cudaStreamWaitEvent(0, eE, 0);
}

// round 16
// speedup vs baseline: 1.5985x; 1.0304x over previous
#include <cuda_runtime.h>
#include <cuda_fp16.h>
#include <math.h>
#include <stdint.h>

#define Nn 8192
#define Dd 512
#define KDIM 512
#define NHEADS 8
#define HDIM 64
#define TOPK 16

// ---------------- scratch (static device globals; no allocation) -------------
__device__ uint16_t g_seqh[2 * Nn * Dd];        // proj+bias+relu out (fp16)
__device__ uint16_t g_qkvh[2 * Nn * 3 * Dd];    // qkv out (fp16)
__device__ uint16_t g_atth[2 * Nn * Dd];        // out-proj out (fp16)
__device__ uint16_t g_Sh[(size_t)Nn * Nn];      // sim logits (fp16, 128 MB)
__device__ float g_hidden[Nn * (Dd / 2)];
__device__ uint16_t g_ah[2 * Nn * Dd];          // activations (fp16)
__device__ uint16_t g_a1h[Nn * Dd];             // proj1 act
__device__ uint16_t g_wp0h[Dd * Dd];
__device__ uint16_t g_wp1h[Dd * Dd];
__device__ uint16_t g_wqh[3 * Dd * Dd];
__device__ uint16_t g_woh[Dd * Dd];
__device__ uint16_t g_weh[(Dd / 2) * Dd];
__device__ uint16_t g_fh[Nn * Dd];              // fused (fp16)

// ============================ PTX helpers ====================================
__device__ __forceinline__ uint32_t smem_u32(const void* p) {
    uint32_t a;
    asm("{ .reg .u64 t; cvta.to.shared.u64 t, %1; cvt.u32.u64 %0, t; }" : "=r"(a) : "l"(p));
    return a;
}
__device__ __forceinline__ void cp16(uint32_t dst, const void* src) {
    asm volatile("cp.async.cg.shared.global [%0], [%1], 16;" :: "r"(dst), "l"(src) : "memory");
}
__device__ __forceinline__ void cp_commit() {
    asm volatile("cp.async.commit_group;" ::: "memory");
}
template <int N> __device__ __forceinline__ void cp_wait() {
    asm volatile("cp.async.wait_group %0;" :: "n"(N) : "memory");
}
__device__ __forceinline__ void ldsm4(uint32_t* r, uint32_t a) {
    asm volatile("ldmatrix.sync.aligned.m8n8.x4.shared.b16 {%0,%1,%2,%3}, [%4];"
                 : "=r"(r[0]), "=r"(r[1]), "=r"(r[2]), "=r"(r[3]) : "r"(a));
}
__device__ __forceinline__ void mma16816(float* c, const uint32_t* a, uint32_t b0, uint32_t b1) {
    asm volatile("mma.sync.aligned.m16n8k16.row.col.f32.f16.f16.f32 "
                 "{%0,%1,%2,%3}, {%4,%5,%6,%7}, {%8,%9}, {%0,%1,%2,%3};"
                 : "+f"(c[0]), "+f"(c[1]), "+f"(c[2]), "+f"(c[3])
                 : "r"(a[0]), "r"(a[1]), "r"(a[2]), "r"(a[3]), "r"(b0), "r"(b1));
}

// ======================= warp-MMA NT GEMM (fp16, fp32 acc) ===================
// HALF_OUT: write C as fp16 (__half2), else fp32 (float2).
template <int RELU, int HAS_BIAS, int HALF_OUT>
__global__ __launch_bounds__(128, 2) void tgemm(
    const uint16_t* __restrict__ Ap, const uint16_t* __restrict__ Bp,
    const float* __restrict__ bias, void* __restrict__ Cv, int ldc)
{
    __shared__ uint16_t sA[2][128 * 32];
    __shared__ uint16_t sB[2][128 * 32];

    const int tid = threadIdx.x;
    const int lane = tid & 31, wid = tid >> 5;
    const int wm = wid & 1;
    const int wn = wid >> 1;
    const int bm = blockIdx.y * 128, bn = blockIdx.x * 128;

    const uint32_t sa0 = smem_u32(&sA[0][0]), sa1 = smem_u32(&sA[1][0]);
    const uint32_t sb0 = smem_u32(&sB[0][0]), sb1 = smem_u32(&sB[1][0]);

    const int NCHK = KDIM / 32;

    uint32_t lsw[4]; size_t lsrc[4];
#pragma unroll
    for (int i = 0; i < 4; i++) {
        int s = tid + 128 * i;
        int r = s >> 2, c = s & 3;
        lsw[i] = r * 64 + (((c ^ ((r >> 1) & 3))) << 4);
        lsrc[i] = (size_t)r * KDIM + c * 8;
    }

    uint32_t offA[2][4], offB[2][4];
#pragma unroll
    for (int kk = 0; kk < 2; kk++) {
#pragma unroll
        for (int f = 0; f < 4; f++) {
            int r = wm * 64 + f * 16 + (lane & 15);
            int c = kk * 2 + (lane >> 4);
            offA[kk][f] = r * 64 + (((c ^ ((r >> 1) & 3))) << 4);
        }
#pragma unroll
        for (int g = 0; g < 4; g++) {
            int r = wn * 64 + g * 16 + (lane & 7) + ((lane >> 4) << 3);
            int c = kk * 2 + ((lane >> 3) & 1);
            offB[kk][g] = r * 64 + (((c ^ ((r >> 1) & 3))) << 4);
        }
    }

    float acc[4][8][4];
#pragma unroll
    for (int f = 0; f < 4; f++)
#pragma unroll
        for (int g = 0; g < 8; g++)
#pragma unroll
            for (int j = 0; j < 4; j++) acc[f][g][j] = 0.f;

    auto load_chunk = [&](int c, int buf) {
        const int k0 = c * 32;
        const uint32_t da = buf ? sa1 : sa0;
        const uint32_t db = buf ? sb1 : sb0;
#pragma unroll
        for (int i = 0; i < 4; i++) {
            cp16(da + lsw[i], Ap + (size_t)bm * KDIM + k0 + lsrc[i]);
            cp16(db + lsw[i], Bp + (size_t)bn * KDIM + k0 + lsrc[i]);
        }
        cp_commit();
    };

    load_chunk(0, 0);

    for (int c = 0; c < NCHK; c++) {
        const int b = c & 1;
        if (c + 1 < NCHK) { load_chunk(c + 1, b ^ 1); cp_wait<1>(); }
        else cp_wait<0>();
        __syncthreads();

        const uint32_t da = b ? sa1 : sa0;
        const uint32_t db = b ? sb1 : sb0;
#pragma unroll
        for (int kk = 0; kk < 2; kk++) {
            uint32_t ra[4][4], rb[4][4];
#pragma unroll
            for (int f = 0; f < 4; f++) ldsm4(ra[f], da + offA[kk][f]);
#pragma unroll
            for (int g = 0; g < 4; g++) ldsm4(rb[g], db + offB[kk][g]);
#pragma unroll
            for (int f = 0; f < 4; f++)
#pragma unroll
                for (int g = 0; g < 4; g++) {
                    mma16816(acc[f][2 * g + 0], ra[f], rb[g][0], rb[g][1]);
                    mma16816(acc[f][2 * g + 1], ra[f], rb[g][2], rb[g][3]);
                }
        }
        __syncthreads();
    }

    const int col0 = bn + wn * 64 + (lane & 3) * 2;
#pragma unroll
    for (int f = 0; f < 4; f++) {
        const int row0 = bm + wm * 64 + f * 16 + (lane >> 2);
#pragma unroll
        for (int g = 0; g < 8; g++) {
            const int col = col0 + g * 8;
            float b0 = 0.f, b1 = 0.f;
            if (HAS_BIAS) { b0 = bias[col]; b1 = bias[col + 1]; }
            float2 v0, v1;
            v0.x = acc[f][g][0] + b0; v0.y = acc[f][g][1] + b1;
            v1.x = acc[f][g][2] + b0; v1.y = acc[f][g][3] + b1;
            if (RELU) {
                v0.x = fmaxf(v0.x, 0.f); v0.y = fmaxf(v0.y, 0.f);
                v1.x = fmaxf(v1.x, 0.f); v1.y = fmaxf(v1.y, 0.f);
            }
            if (HALF_OUT) {
                uint16_t* Ch = (uint16_t*)Cv;
                *(__half2*)(Ch + (size_t)row0 * ldc + col) = __floats2half2_rn(v0.x, v0.y);
                *(__half2*)(Ch + (size_t)(row0 + 8) * ldc + col) = __floats2half2_rn(v1.x, v1.y);
            } else {
                float* Cf = (float*)Cv;
                *(float2*)(Cf + (size_t)row0 * ldc + col) = v0;
                *(float2*)(Cf + (size_t)(row0 + 8) * ldc + col) = v1;
            }
        }
    }
}

// ============== symmetric variant: S = F*F^T (fp16 out), upper blocks ========
__global__ __launch_bounds__(128, 2) void tgemm_sym(
    const uint16_t* __restrict__ Fp, uint16_t* __restrict__ C)
{
    __shared__ __align__(16) uint8_t smraw[32768];
    float* smT = (float*)smraw;

    const int tid = threadIdx.x;
    const int lane = tid & 31, wid = tid >> 5;
    const int wm = wid & 1;
    const int wn = wid >> 1;

    int t = blockIdx.x;
    int bj = (int)((sqrtf(8.f * t + 1.f) - 1.f) * 0.5f);
    while ((bj + 1) * (bj + 2) / 2 <= t) bj++;
    while (bj * (bj + 1) / 2 > t) bj--;
    int bi = t - bj * (bj + 1) / 2;
    const int bm = bi * 128, bn = bj * 128;

    const uint32_t sa0 = smem_u32(smraw), sa1 = smem_u32(smraw + 8192);
    const uint32_t sb0 = smem_u32(smraw + 16384), sb1 = smem_u32(smraw + 24576);

    const int NCHK = KDIM / 32;

    uint32_t lsw[4]; size_t lsrc[4];
#pragma unroll
    for (int i = 0; i < 4; i++) {
        int s = tid + 128 * i;
        int r = s >> 2, c = s & 3;
        lsw[i] = r * 64 + (((c ^ ((r >> 1) & 3))) << 4);
        lsrc[i] = (size_t)r * KDIM + c * 8;
    }

    uint32_t offA[2][4], offB[2][4];
#pragma unroll
    for (int kk = 0; kk < 2; kk++) {
#pragma unroll
        for (int f = 0; f < 4; f++) {
            int r = wm * 64 + f * 16 + (lane & 15);
            int c = kk * 2 + (lane >> 4);
            offA[kk][f] = r * 64 + (((c ^ ((r >> 1) & 3))) << 4);
        }
#pragma unroll
        for (int g = 0; g < 4; g++) {
            int r = wn * 64 + g * 16 + (lane & 7) + ((lane >> 4) << 3);
            int c = kk * 2 + ((lane >> 3) & 1);
            offB[kk][g] = r * 64 + (((c ^ ((r >> 1) & 3))) << 4);
        }
    }

    float acc[4][8][4];
#pragma unroll
    for (int f = 0; f < 4; f++)
#pragma unroll
        for (int g = 0; g < 8; g++)
#pragma unroll
            for (int j = 0; j < 4; j++) acc[f][g][j] = 0.f;

    auto load_chunk = [&](int c, int buf) {
        const int k0 = c * 32;
        const uint32_t da = buf ? sa1 : sa0;
        const uint32_t db = buf ? sb1 : sb0;
#pragma unroll
        for (int i = 0; i < 4; i++) {
            cp16(da + lsw[i], Fp + (size_t)bm * KDIM + k0 + lsrc[i]);
            cp16(db + lsw[i], Fp + (size_t)bn * KDIM + k0 + lsrc[i]);
        }
        cp_commit();
    };

    load_chunk(0, 0);

    for (int c = 0; c < NCHK; c++) {
        const int b = c & 1;
        if (c + 1 < NCHK) { load_chunk(c + 1, b ^ 1); cp_wait<1>(); }
        else cp_wait<0>();
        __syncthreads();

        const uint32_t da = b ? sa1 : sa0;
        const uint32_t db = b ? sb1 : sb0;
#pragma unroll
        for (int kk = 0; kk < 2; kk++) {
            uint32_t ra[4][4], rb[4][4];
#pragma unroll
            for (int f = 0; f < 4; f++) ldsm4(ra[f], da + offA[kk][f]);
#pragma unroll
            for (int g = 0; g < 4; g++) ldsm4(rb[g], db + offB[kk][g]);
#pragma unroll
            for (int f = 0; f < 4; f++)
#pragma unroll
                for (int g = 0; g < 4; g++) {
                    mma16816(acc[f][2 * g + 0], ra[f], rb[g][0], rb[g][1]);
                    mma16816(acc[f][2 * g + 1], ra[f], rb[g][2], rb[g][3]);
                }
        }
        __syncthreads();
    }

    // upper tile write (fp16)
    const int col0 = bn + wn * 64 + (lane & 3) * 2;
#pragma unroll
    for (int f = 0; f < 4; f++) {
        const int row0 = bm + wm * 64 + f * 16 + (lane >> 2);
#pragma unroll
        for (int g = 0; g < 8; g++) {
            const int col = col0 + g * 8;
            *(__half2*)(C + (size_t)row0 * Nn + col) =
                __floats2half2_rn(acc[f][g][0], acc[f][g][1]);
            *(__half2*)(C + (size_t)(row0 + 8) * Nn + col) =
                __floats2half2_rn(acc[f][g][2], acc[f][g][3]);
        }
    }

    // mirrored (lower) tile write via smem transpose, coalesced, fp16
    if (bi != bj) {
#pragma unroll
        for (int cc = 0; cc < 2; cc++) {
            __syncthreads();
            float* buf = smT + wn * (32 * 128);
#pragma unroll
            for (int gl = 0; gl < 4; gl++) {
                const int g = cc * 4 + gl;
                const int cl = gl * 8 + (lane & 3) * 2;
#pragma unroll
                for (int f = 0; f < 4; f++) {
                    const int r = wm * 64 + f * 16 + (lane >> 2);
                    buf[cl * 128 + r]           = acc[f][g][0];
                    buf[(cl + 1) * 128 + r]     = acc[f][g][1];
                    buf[cl * 128 + r + 8]       = acc[f][g][2];
                    buf[(cl + 1) * 128 + r + 8] = acc[f][g][3];
                }
            }
            __syncthreads();
            for (int idx = tid; idx < 64 * 32; idx += 128) {
                const int rr = idx >> 5;
                const int sg = idx & 31;
                const int b2 = rr >> 5;
                const int cl = rr & 31;
                const int cAbs = bn + b2 * 64 + cc * 32 + cl;
                float4 v = *(float4*)(smT + b2 * (32 * 128) + cl * 128 + sg * 4);
                union { __half2 h[2]; uint2 u; } cv;
                cv.h[0] = __floats2half2_rn(v.x, v.y);
                cv.h[1] = __floats2half2_rn(v.z, v.w);
                *(uint2*)(C + (size_t)cAbs * Nn + bm + sg * 4) = cv.u;
            }
        }
    }
}

// ---------------- fp32 -> fp16 convert ---------------------------------------
__global__ void split_kernel(const float* __restrict__ x, uint16_t* __restrict__ hi,
                             int n4)
{
    int i = blockIdx.x * blockDim.x + threadIdx.x;
    if (i >= n4) return;
    float4 v = ((const float4*)x)[i];
    ushort4 hv;
    hv.x = __half_as_ushort(__float2half_rn(v.x));
    hv.y = __half_as_ushort(__float2half_rn(v.y));
    hv.z = __half_as_ushort(__float2half_rn(v.z));
    hv.w = __half_as_ushort(__float2half_rn(v.w));
    ((ushort4*)hi)[i] = hv;
}

// ---------------- LayerNorm (fp16 in) -> fp16 act ----------------------------
__global__ void ln_kernel(const float* __restrict__ g0, const float* __restrict__ be0,
                          const float* __restrict__ g1, const float* __restrict__ be1)
{
    int row = blockIdx.x;
    const uint16_t* x = g_seqh + (size_t)row * Dd;
    int tid = threadIdx.x;
    float v0 = __half2float(__ushort_as_half(x[tid]));
    float v1 = __half2float(__ushort_as_half(x[tid + 256]));
    __shared__ float rs[256], rq[256];
    rs[tid] = v0 + v1;
    rq[tid] = v0 * v0 + v1 * v1;
    __syncthreads();
    for (int st = 128; st > 0; st >>= 1) {
        if (tid < st) { rs[tid] += rs[tid + st]; rq[tid] += rq[tid + st]; }
        __syncthreads();
    }
    float mean = rs[0] * (1.f / Dd);
    float var = rq[0] * (1.f / Dd) - mean * mean;
    float inv = rsqrtf(var + 1e-5f);
    const float* gg = (row & 1) ? g1 : g0;
    const float* bb = (row & 1) ? be1 : be0;
    float y0 = (v0 - mean) * inv * gg[tid] + bb[tid];
    float y1 = (v1 - mean) * inv * gg[tid + 256] + bb[tid + 256];
    size_t base = (size_t)row * Dd;
    g_ah[base + tid]       = __half_as_ushort(__float2half_rn(y0));
    g_ah[base + tid + 256] = __half_as_ushort(__float2half_rn(y1));
}

// ---------------- 2-token multihead attention (fp16 qkv) -> ctx fp16 ---------
__global__ void attn_kernel()
{
    int gt = blockIdx.x * blockDim.x + threadIdx.x;
    int gw = gt >> 5, lane = gt & 31;
    if (gw >= Nn * NHEADS) return;
    int node = gw >> 3, h = gw & 7;
    const uint16_t* base = g_qkvh + (size_t)node * 2 * (3 * Dd);
    int d0 = lane * 2;
    float q[2][2], k[2][2], v[2][2];
#pragma unroll
    for (int t = 0; t < 2; t++) {
        const uint16_t* r = base + t * (3 * Dd) + h * HDIM;
        float2 qq = __half22float2(*(const __half2*)(r + d0));
        float2 kk = __half22float2(*(const __half2*)(r + Dd + d0));
        float2 vv = __half22float2(*(const __half2*)(r + 2 * Dd + d0));
        q[t][0] = qq.x; q[t][1] = qq.y;
        k[t][0] = kk.x; k[t][1] = kk.y;
        v[t][0] = vv.x; v[t][1] = vv.y;
    }
    float s[2][2];
#pragma unroll
    for (int qi = 0; qi < 2; qi++)
#pragma unroll
        for (int ki = 0; ki < 2; ki++)
            s[qi][ki] = q[qi][0] * k[ki][0] + q[qi][1] * k[ki][1];
#pragma unroll
    for (int o = 16; o > 0; o >>= 1)
#pragma unroll
        for (int qi = 0; qi < 2; qi++)
#pragma unroll
            for (int ki = 0; ki < 2; ki++)
                s[qi][ki] += __shfl_xor_sync(0xffffffffu, s[qi][ki], o);
    const float scale = 0.125f;
#pragma unroll
    for (int qi = 0; qi < 2; qi++) {
        float a0 = s[qi][0] * scale, a1 = s[qi][1] * scale;
        float m = fmaxf(a0, a1);
        float e0 = __expf(a0 - m), e1 = __expf(a1 - m);
        float inv = 1.f / (e0 + e1);
        float w0 = e0 * inv, w1 = e1 * inv;
        float o0 = w0 * v[0][0] + w1 * v[1][0];
        float o1 = w0 * v[0][1] + w1 * v[1][1];
        size_t off = (size_t)(node * 2 + qi) * Dd + h * HDIM + d0;
        *(__half2*)(g_ah + off) = __floats2half2_rn(o0, o1);
    }
}

// ---------------- mean over the 2 tokens (fp16 in) -> fused fp16 -------------
__global__ void mean_kernel()
{
    int i = blockIdx.x * blockDim.x + threadIdx.x;
    if (i >= Nn * Dd / 4) return;
    int e0 = i * 4;
    int node = e0 / Dd, d = e0 - node * Dd;
    const uint16_t* r0 = g_atth + (size_t)(node * 2) * Dd + d;
    const uint16_t* r1 = g_atth + (size_t)(node * 2 + 1) * Dd + d;
    __half2 a0 = *(const __half2*)(r0);
    __half2 a1 = *(const __half2*)(r0 + 2);
    __half2 b0 = *(const __half2*)(r1);
    __half2 b1 = *(const __half2*)(r1 + 2);
    float2 fa0 = __half22float2(a0), fa1 = __half22float2(a1);
    float2 fb0 = __half22float2(b0), fb1 = __half22float2(b1);
    __half2 h0 = __floats2half2_rn(0.5f * (fa0.x + fb0.x), 0.5f * (fa0.y + fb0.y));
    __half2 h1 = __floats2half2_rn(0.5f * (fa1.x + fb1.x), 0.5f * (fa1.y + fb1.y));
    *(__half2*)(g_fh + (size_t)e0)     = h0;
    *(__half2*)(g_fh + (size_t)e0 + 2) = h1;
}

// ---------------- softmax stats + top-16 via segment-max hierarchy ----------
// S stored fp16; widened to fp32 in smem (identical comparison semantics on
// the quantized values).
__global__ void topk_kernel(float* __restrict__ Hout)
{
    int row = blockIdx.x;
    extern __shared__ float sh[];                 // Nn floats + 256 segmax
    float* segmax = sh + Nn;
    __shared__ float swv[8];
    __shared__ int swi[8];
    __shared__ float s_bcast;
    __shared__ int s_seg;
    __shared__ float topv[TOPK];
    __shared__ int topi[TOPK];
    const uint16_t* srow = g_Sh + (size_t)row * Nn;
    int tid = threadIdx.x;
    int lane = tid & 31, wid = tid >> 5;

    // vectorized fp16 row load (uint4 = 8 halves), widen to fp32 smem
    for (int j8 = tid; j8 < Nn / 8; j8 += 256) {
        uint4 raw = ((const uint4*)srow)[j8];
        float2 f0 = __half22float2(*(__half2*)&raw.x);
        float2 f1 = __half22float2(*(__half2*)&raw.y);
        float2 f2 = __half22float2(*(__half2*)&raw.z);
        float2 f3 = __half22float2(*(__half2*)&raw.w);
        float4 o0 = make_float4(f0.x, f0.y, f1.x, f1.y);
        float4 o1 = make_float4(f2.x, f2.y, f3.x, f3.y);
        *(float4*)(sh + j8 * 8)     = o0;
        *(float4*)(sh + j8 * 8 + 4) = o1;
    }
    __syncthreads();

    {
        const int base = tid * 32;
        float sm = -INFINITY;
#pragma unroll 8
        for (int i = 0; i < 32; i++)
            sm = fmaxf(sm, sh[base + ((i + tid) & 31)]);
        segmax[tid] = sm;
        float lmax = sm;
#pragma unroll
        for (int o = 16; o > 0; o >>= 1)
            lmax = fmaxf(lmax, __shfl_xor_sync(0xffffffffu, lmax, o));
        if (lane == 0) swv[wid] = lmax;
    }
    __syncthreads();
    if (tid == 0) {
        float m = swv[0];
#pragma unroll
        for (int w = 1; w < 8; w++) m = fmaxf(m, swv[w]);
        s_bcast = m;
    }
    __syncthreads();
    const float rmax = s_bcast;

    float lsum = 0.f;
    for (int j4 = tid; j4 < Nn / 4; j4 += 256) {
        float4 v = *(float4*)(sh + j4 * 4);
        lsum += __expf(v.x - rmax) + __expf(v.y - rmax)
              + __expf(v.z - rmax) + __expf(v.w - rmax);
    }
#pragma unroll
    for (int o = 16; o > 0; o >>= 1)
        lsum += __shfl_xor_sync(0xffffffffu, lsum, o);
    if (lane == 0) swv[wid] = lsum;
    __syncthreads();
    if (tid == 0) {
        float s = 0.f;
#pragma unroll
        for (int w = 0; w < 8; w++) s += swv[w];
        s_bcast = 1.f / s;
    }
    __syncthreads();
    const float rinv = s_bcast;

    for (int kk = 0; kk < TOPK; kk++) {
        float v = segmax[tid];
        int idx = tid;
#pragma unroll
        for (int o = 16; o > 0; o >>= 1) {
            float ov = __shfl_xor_sync(0xffffffffu, v, o);
            int oi = __shfl_xor_sync(0xffffffffu, idx, o);
            if (ov > v || (ov == v && oi < idx)) { v = ov; idx = oi; }
        }
        if (lane == 0) { swv[wid] = v; swi[wid] = idx; }
        __syncthreads();
        if (tid == 0) {
            float bv = swv[0]; int bi = swi[0];
#pragma unroll
            for (int w = 1; w < 8; w++)
                if (swv[w] > bv || (swv[w] == bv && swi[w] < bi)) { bv = swv[w]; bi = swi[w]; }
            s_seg = bi;
        }
        __syncthreads();
        const int s = s_seg;
        if (wid == 0) {
            int ei = s * 32 + lane;
            float ev = sh[ei];
            float v2 = ev; int i2 = ei;
#pragma unroll
            for (int o = 16; o > 0; o >>= 1) {
                float ov = __shfl_xor_sync(0xffffffffu, v2, o);
                int oi = __shfl_xor_sync(0xffffffffu, i2, o);
                if (ov > v2 || (ov == v2 && oi < i2)) { v2 = ov; i2 = oi; }
            }
            if (lane == 0) { topv[kk] = v2; topi[kk] = i2; }
            float nv = (ei == i2) ? -INFINITY : ev;
            if (ei == i2) sh[ei] = -INFINITY;
            float mx = nv;
#pragma unroll
            for (int o = 16; o > 0; o >>= 1)
                mx = fmaxf(mx, __shfl_xor_sync(0xffffffffu, mx, o));
            if (lane == 0) segmax[s] = mx;
        }
        __syncthreads();
    }

    if (tid == 0) {
        Hout[(size_t)row * Nn + row] = 1.0f;
#pragma unroll
        for (int kk = 0; kk < TOPK; kk++)
            Hout[(size_t)topi[kk] * Nn + row] = __expf(topv[kk] - rmax) * rinv;
    }
}

__global__ void ew_kernel(const float* __restrict__ w2, const float* __restrict__ b2,
                          float* __restrict__ out)
{
    int gt = blockIdx.x * blockDim.x + threadIdx.x;
    int gw = gt >> 5, lane = gt & 31;
    if (gw >= Nn) return;
    const float* hrow = g_hidden + (size_t)gw * (Dd / 2);
    float s = 0.f;
    for (int j = lane; j < Dd / 2; j += 32) s += hrow[j] * w2[j];
#pragma unroll
    for (int o = 16; o > 0; o >>= 1) s += __shfl_xor_sync(0xffffffffu, s, o);
    if (lane == 0) {
        float v = s + b2[0];
        float sig = 1.f / (1.f + __expf(-v));
        out[gw] = fmaxf(sig, 1e-8f);
    }
}

// ---------------- launch ------------------------------------------------------
static void do_split_s(const float* src, uint16_t* hi, size_t n, cudaStream_t st)
{
    int n4 = (int)(n / 4);
    split_kernel<<<(n4 + 255) / 256, 256, 0, st>>>(src, hi, n4);
}

extern "C" void kernel_launch(void* const* d_in, const int* in_sizes, int n_in,
                              void* d_out, int out_size)
{
    const float* x0    = (const float*)d_in[0];
    const float* x1    = (const float*)d_in[1];
    const float* w_p0  = (const float*)d_in[2];
    const float* b_p0  = (const float*)d_in[3];
    const float* gg0   = (const float*)d_in[4];
    const float* be0   = (const float*)d_in[5];
    const float* w_p1  = (const float*)d_in[6];
    const float* b_p1  = (const float*)d_in[7];
    const float* gg1   = (const float*)d_in[8];
    const float* be1   = (const float*)d_in[9];
    const float* in_w  = (const float*)d_in[10];
    const float* in_b  = (const float*)d_in[11];
    const float* out_w = (const float*)d_in[12];
    const float* out_b = (const float*)d_in[13];
    const float* ew_w1 = (const float*)d_in[14];
    const float* ew_b1 = (const float*)d_in[15];
    const float* ew_w2 = (const float*)d_in[16];
    const float* ew_b2 = (const float*)d_in[17];

    float* H  = (float*)d_out;
    float* ew = H + (size_t)Nn * Nn;

    float *hidden;
    uint16_t *seqh, *qkvh, *atth, *Sh;
    uint16_t *ah, *a1h, *fh;
    uint16_t *wp0h, *wp1h, *wqh, *woh, *weh;
    cudaGetSymbolAddress((void**)&seqh, g_seqh);
    cudaGetSymbolAddress((void**)&qkvh, g_qkvh);
    cudaGetSymbolAddress((void**)&atth, g_atth);
    cudaGetSymbolAddress((void**)&Sh, g_Sh);
    cudaGetSymbolAddress((void**)&hidden, g_hidden);
    cudaGetSymbolAddress((void**)&ah, g_ah);
    cudaGetSymbolAddress((void**)&a1h, g_a1h);
    cudaGetSymbolAddress((void**)&wp0h, g_wp0h);
    cudaGetSymbolAddress((void**)&wp1h, g_wp1h);
    cudaGetSymbolAddress((void**)&wqh, g_wqh);
    cudaGetSymbolAddress((void**)&woh, g_woh);
    cudaGetSymbolAddress((void**)&weh, g_weh);
    cudaGetSymbolAddress((void**)&fh, g_fh);

    static cudaStream_t s1 = nullptr, s2 = nullptr;
    static cudaEvent_t eF = nullptr, eS2 = nullptr, eP1 = nullptr, eM = nullptr, eE = nullptr;
    if (!s1) {
        cudaStreamCreateWithFlags(&s1, cudaStreamNonBlocking);
        cudaStreamCreateWithFlags(&s2, cudaStreamNonBlocking);
        cudaEventCreateWithFlags(&eF,  cudaEventDisableTiming);
        cudaEventCreateWithFlags(&eS2, cudaEventDisableTiming);
        cudaEventCreateWithFlags(&eP1, cudaEventDisableTiming);
        cudaEventCreateWithFlags(&eM,  cudaEventDisableTiming);
        cudaEventCreateWithFlags(&eE,  cudaEventDisableTiming);
    }

    // fork from capture (default) stream
    cudaEventRecord(eF, 0);
    cudaStreamWaitEvent(s1, eF, 0);
    cudaStreamWaitEvent(s2, eF, 0);

    // s2: H memset + weight converts (input-only)
    cudaMemsetAsync(H, 0, (size_t)Nn * Nn * sizeof(float), s2);
    do_split_s(in_w,  wqh, (size_t)3 * Dd * Dd, s2);
    do_split_s(out_w, woh, (size_t)Dd * Dd, s2);
    do_split_s(ew_w1, weh, (size_t)(Dd / 2) * Dd, s2);
    cudaEventRecord(eS2, s2);

    // s1: modality-1 projection chain (fp16 out into interleaved seqh)
    do_split_s(x1,   a1h,  (size_t)Nn * Dd, s1);
    do_split_s(w_p1, wp1h, (size_t)Dd * Dd, s1);
    tgemm<1, 1, 1><<<dim3(Dd / 128, Nn / 128), 128, 0, s1>>>(a1h, wp1h, b_p1, seqh + Dd, 2 * Dd);
    cudaEventRecord(eP1, s1);

    // stream 0: modality-0 projection chain
    do_split_s(x0,   ah,   (size_t)Nn * Dd, 0);
    do_split_s(w_p0, wp0h, (size_t)Dd * Dd, 0);
    tgemm<1, 1, 1><<<dim3(Dd / 128, Nn / 128), 128>>>(ah, wp0h, b_p0, seqh, 2 * Dd);

    // join proj1 + weight converts, trunk on stream 0
    cudaStreamWaitEvent(0, eP1, 0);
    ln_kernel<<<2 * Nn, 256>>>(gg0, be0, gg1, be1);
    cudaStreamWaitEvent(0, eS2, 0);
    tgemm<0, 1, 1><<<dim3(3 * Dd / 128, 2 * Nn / 128), 128>>>(ah, wqh, in_b, qkvh, 3 * Dd);
    attn_kernel<<<(Nn * NHEADS * 32) / 256, 256>>>();
    tgemm<0, 1, 1><<<dim3(Dd / 128, 2 * Nn / 128), 128>>>(ah, woh, out_b, atth, Dd);
    mean_kernel<<<(Nn * Dd / 4 + 255) / 256, 256>>>();
    cudaEventRecord(eM, 0);

    // s1: edge-weight MLP (parallel to sim GEMM + topk)
    cudaStreamWaitEvent(s1, eM, 0);
    tgemm<1, 1, 0><<<dim3((Dd / 2) / 128, Nn / 128), 128, 0, s1>>>(fh, weh, ew_b1, hidden, Dd / 2);
    ew_kernel<<<(Nn * 32) / 256, 256, 0, s1>>>(ew_w2, ew_b2, ew);
    cudaEventRecord(eE, s1);

    // stream 0: similarity GEMM (symmetric, fp16 S) + topk
    tgemm_sym<<<(Nn / 128) * (Nn / 128 + 1) / 2, 128>>>(fh, Sh);
    topk_kernel<<<Nn, 256, (Nn + 256) * sizeof(float)>>>(H);

    // join ew branch back into capture stream
    cudaStreamWaitEvent(0, eE, 0);
}

// round 17
// speedup vs baseline: 1.6170x; 1.0116x over previous
#include <cuda_runtime.h>
#include <cuda_fp16.h>
#include <math.h>
#include <stdint.h>

#define Nn 8192
#define Dd 512
#define KDIM 512
#define NHEADS 8
#define HDIM 64
#define TOPK 16

// ---------------- scratch (static device globals; no allocation) -------------
__device__ uint16_t g_seqh[2 * Nn * Dd];        // proj+bias+relu out (fp16)
__device__ uint16_t g_qkvh[2 * Nn * 3 * Dd];    // qkv out (fp16)
__device__ uint16_t g_Sh[(size_t)Nn * Nn];      // sim logits (fp16, 128 MB)
__device__ float g_hidden[Nn * (Dd / 2)];
__device__ uint16_t g_ah[2 * Nn * Dd];          // activations (fp16)
__device__ uint16_t g_a1h[Nn * Dd];             // proj1 act
__device__ uint16_t g_wp0h[Dd * Dd];
__device__ uint16_t g_wp1h[Dd * Dd];
__device__ uint16_t g_wqh[3 * Dd * Dd];
__device__ uint16_t g_woh[Dd * Dd];
__device__ uint16_t g_weh[(Dd / 2) * Dd];
__device__ uint16_t g_fh[Nn * Dd];              // fused (fp16)

// ============================ PTX helpers ====================================
__device__ __forceinline__ uint32_t smem_u32(const void* p) {
    uint32_t a;
    asm("{ .reg .u64 t; cvta.to.shared.u64 t, %1; cvt.u32.u64 %0, t; }" : "=r"(a) : "l"(p));
    return a;
}
__device__ __forceinline__ void cp16(uint32_t dst, const void* src) {
    asm volatile("cp.async.cg.shared.global [%0], [%1], 16;" :: "r"(dst), "l"(src) : "memory");
}
__device__ __forceinline__ void cp_commit() {
    asm volatile("cp.async.commit_group;" ::: "memory");
}
template <int N> __device__ __forceinline__ void cp_wait() {
    asm volatile("cp.async.wait_group %0;" :: "n"(N) : "memory");
}
__device__ __forceinline__ void ldsm4(uint32_t* r, uint32_t a) {
    asm volatile("ldmatrix.sync.aligned.m8n8.x4.shared.b16 {%0,%1,%2,%3}, [%4];"
                 : "=r"(r[0]), "=r"(r[1]), "=r"(r[2]), "=r"(r[3]) : "r"(a));
}
__device__ __forceinline__ void mma16816(float* c, const uint32_t* a, uint32_t b0, uint32_t b1) {
    asm volatile("mma.sync.aligned.m16n8k16.row.col.f32.f16.f16.f32 "
                 "{%0,%1,%2,%3}, {%4,%5,%6,%7}, {%8,%9}, {%0,%1,%2,%3};"
                 : "+f"(c[0]), "+f"(c[1]), "+f"(c[2]), "+f"(c[3])
                 : "r"(a[0]), "r"(a[1]), "r"(a[2]), "r"(a[3]), "r"(b0), "r"(b1));
}

// ======================= warp-MMA NT GEMM (fp16, fp32 acc) ===================
// HALF_OUT: write C as fp16. MEANPAIR: average adjacent row pairs (2n,2n+1)
// in-register (shfl_xor 4) and write node rows to C (fp16, ldc = node stride).
template <int RELU, int HAS_BIAS, int HALF_OUT, int MEANPAIR = 0>
__global__ __launch_bounds__(128, 2) void tgemm(
    const uint16_t* __restrict__ Ap, const uint16_t* __restrict__ Bp,
    const float* __restrict__ bias, void* __restrict__ Cv, int ldc)
{
    __shared__ uint16_t sA[2][128 * 32];
    __shared__ uint16_t sB[2][128 * 32];

    const int tid = threadIdx.x;
    const int lane = tid & 31, wid = tid >> 5;
    const int wm = wid & 1;
    const int wn = wid >> 1;
    const int bm = blockIdx.y * 128, bn = blockIdx.x * 128;

    const uint32_t sa0 = smem_u32(&sA[0][0]), sa1 = smem_u32(&sA[1][0]);
    const uint32_t sb0 = smem_u32(&sB[0][0]), sb1 = smem_u32(&sB[1][0]);

    const int NCHK = KDIM / 32;

    uint32_t lsw[4]; size_t lsrc[4];
#pragma unroll
    for (int i = 0; i < 4; i++) {
        int s = tid + 128 * i;
        int r = s >> 2, c = s & 3;
        lsw[i] = r * 64 + (((c ^ ((r >> 1) & 3))) << 4);
        lsrc[i] = (size_t)r * KDIM + c * 8;
    }

    uint32_t offA[2][4], offB[2][4];
#pragma unroll
    for (int kk = 0; kk < 2; kk++) {
#pragma unroll
        for (int f = 0; f < 4; f++) {
            int r = wm * 64 + f * 16 + (lane & 15);
            int c = kk * 2 + (lane >> 4);
            offA[kk][f] = r * 64 + (((c ^ ((r >> 1) & 3))) << 4);
        }
#pragma unroll
        for (int g = 0; g < 4; g++) {
            int r = wn * 64 + g * 16 + (lane & 7) + ((lane >> 4) << 3);
            int c = kk * 2 + ((lane >> 3) & 1);
            offB[kk][g] = r * 64 + (((c ^ ((r >> 1) & 3))) << 4);
        }
    }

    float acc[4][8][4];
#pragma unroll
    for (int f = 0; f < 4; f++)
#pragma unroll
        for (int g = 0; g < 8; g++)
#pragma unroll
            for (int j = 0; j < 4; j++) acc[f][g][j] = 0.f;

    auto load_chunk = [&](int c, int buf) {
        const int k0 = c * 32;
        const uint32_t da = buf ? sa1 : sa0;
        const uint32_t db = buf ? sb1 : sb0;
#pragma unroll
        for (int i = 0; i < 4; i++) {
            cp16(da + lsw[i], Ap + (size_t)bm * KDIM + k0 + lsrc[i]);
            cp16(db + lsw[i], Bp + (size_t)bn * KDIM + k0 + lsrc[i]);
        }
        cp_commit();
    };

    load_chunk(0, 0);

    for (int c = 0; c < NCHK; c++) {
        const int b = c & 1;
        if (c + 1 < NCHK) { load_chunk(c + 1, b ^ 1); cp_wait<1>(); }
        else cp_wait<0>();
        __syncthreads();

        const uint32_t da = b ? sa1 : sa0;
        const uint32_t db = b ? sb1 : sb0;
#pragma unroll
        for (int kk = 0; kk < 2; kk++) {
            uint32_t ra[4][4], rb[4][4];
#pragma unroll
            for (int f = 0; f < 4; f++) ldsm4(ra[f], da + offA[kk][f]);
#pragma unroll
            for (int g = 0; g < 4; g++) ldsm4(rb[g], db + offB[kk][g]);
#pragma unroll
            for (int f = 0; f < 4; f++)
#pragma unroll
                for (int g = 0; g < 4; g++) {
                    mma16816(acc[f][2 * g + 0], ra[f], rb[g][0], rb[g][1]);
                    mma16816(acc[f][2 * g + 1], ra[f], rb[g][2], rb[g][3]);
                }
        }
        __syncthreads();
    }

    const int col0 = bn + wn * 64 + (lane & 3) * 2;
#pragma unroll
    for (int f = 0; f < 4; f++) {
        const int row0 = bm + wm * 64 + f * 16 + (lane >> 2);
#pragma unroll
        for (int g = 0; g < 8; g++) {
            const int col = col0 + g * 8;
            float b0 = 0.f, b1 = 0.f;
            if (HAS_BIAS) { b0 = bias[col]; b1 = bias[col + 1]; }
            float2 v0, v1;
            v0.x = acc[f][g][0] + b0; v0.y = acc[f][g][1] + b1;
            v1.x = acc[f][g][2] + b0; v1.y = acc[f][g][3] + b1;
            if (RELU) {
                v0.x = fmaxf(v0.x, 0.f); v0.y = fmaxf(v0.y, 0.f);
                v1.x = fmaxf(v1.x, 0.f); v1.y = fmaxf(v1.y, 0.f);
            }
            if (MEANPAIR) {
                // pair rows (2n, 2n+1): partner lane differs in bit 2 (row0 +-1)
                float m0x = 0.5f * (v0.x + __shfl_xor_sync(0xffffffffu, v0.x, 4));
                float m0y = 0.5f * (v0.y + __shfl_xor_sync(0xffffffffu, v0.y, 4));
                float m1x = 0.5f * (v1.x + __shfl_xor_sync(0xffffffffu, v1.x, 4));
                float m1y = 0.5f * (v1.y + __shfl_xor_sync(0xffffffffu, v1.y, 4));
                if ((lane & 4) == 0) {        // even rows write node = row/2
                    uint16_t* Ch = (uint16_t*)Cv;
                    int n0 = row0 >> 1;
                    int n1 = (row0 + 8) >> 1;
                    *(__half2*)(Ch + (size_t)n0 * ldc + col) = __floats2half2_rn(m0x, m0y);
                    *(__half2*)(Ch + (size_t)n1 * ldc + col) = __floats2half2_rn(m1x, m1y);
                }
            } else if (HALF_OUT) {
                uint16_t* Ch = (uint16_t*)Cv;
                *(__half2*)(Ch + (size_t)row0 * ldc + col) = __floats2half2_rn(v0.x, v0.y);
                *(__half2*)(Ch + (size_t)(row0 + 8) * ldc + col) = __floats2half2_rn(v1.x, v1.y);
            } else {
                float* Cf = (float*)Cv;
                *(float2*)(Cf + (size_t)row0 * ldc + col) = v0;
                *(float2*)(Cf + (size_t)(row0 + 8) * ldc + col) = v1;
            }
        }
    }
}

// ============== symmetric variant: S = F*F^T (fp16 out), upper blocks ========
__global__ __launch_bounds__(128, 2) void tgemm_sym(
    const uint16_t* __restrict__ Fp, uint16_t* __restrict__ C)
{
    __shared__ __align__(16) uint8_t smraw[32768];
    float* smT = (float*)smraw;

    const int tid = threadIdx.x;
    const int lane = tid & 31, wid = tid >> 5;
    const int wm = wid & 1;
    const int wn = wid >> 1;

    int t = blockIdx.x;
    int bj = (int)((sqrtf(8.f * t + 1.f) - 1.f) * 0.5f);
    while ((bj + 1) * (bj + 2) / 2 <= t) bj++;
    while (bj * (bj + 1) / 2 > t) bj--;
    int bi = t - bj * (bj + 1) / 2;
    const int bm = bi * 128, bn = bj * 128;

    const uint32_t sa0 = smem_u32(smraw), sa1 = smem_u32(smraw + 8192);
    const uint32_t sb0 = smem_u32(smraw + 16384), sb1 = smem_u32(smraw + 24576);

    const int NCHK = KDIM / 32;

    uint32_t lsw[4]; size_t lsrc[4];
#pragma unroll
    for (int i = 0; i < 4; i++) {
        int s = tid + 128 * i;
        int r = s >> 2, c = s & 3;
        lsw[i] = r * 64 + (((c ^ ((r >> 1) & 3))) << 4);
        lsrc[i] = (size_t)r * KDIM + c * 8;
    }

    uint32_t offA[2][4], offB[2][4];
#pragma unroll
    for (int kk = 0; kk < 2; kk++) {
#pragma unroll
        for (int f = 0; f < 4; f++) {
            int r = wm * 64 + f * 16 + (lane & 15);
            int c = kk * 2 + (lane >> 4);
            offA[kk][f] = r * 64 + (((c ^ ((r >> 1) & 3))) << 4);
        }
#pragma unroll
        for (int g = 0; g < 4; g++) {
            int r = wn * 64 + g * 16 + (lane & 7) + ((lane >> 4) << 3);
            int c = kk * 2 + ((lane >> 3) & 1);
            offB[kk][g] = r * 64 + (((c ^ ((r >> 1) & 3))) << 4);
        }
    }

    float acc[4][8][4];
#pragma unroll
    for (int f = 0; f < 4; f++)
#pragma unroll
        for (int g = 0; g < 8; g++)
#pragma unroll
            for (int j = 0; j < 4; j++) acc[f][g][j] = 0.f;

    auto load_chunk = [&](int c, int buf) {
        const int k0 = c * 32;
        const uint32_t da = buf ? sa1 : sa0;
        const uint32_t db = buf ? sb1 : sb0;
#pragma unroll
        for (int i = 0; i < 4; i++) {
            cp16(da + lsw[i], Fp + (size_t)bm * KDIM + k0 + lsrc[i]);
            cp16(db + lsw[i], Fp + (size_t)bn * KDIM + k0 + lsrc[i]);
        }
        cp_commit();
    };

    load_chunk(0, 0);

    for (int c = 0; c < NCHK; c++) {
        const int b = c & 1;
        if (c + 1 < NCHK) { load_chunk(c + 1, b ^ 1); cp_wait<1>(); }
        else cp_wait<0>();
        __syncthreads();

        const uint32_t da = b ? sa1 : sa0;
        const uint32_t db = b ? sb1 : sb0;
#pragma unroll
        for (int kk = 0; kk < 2; kk++) {
            uint32_t ra[4][4], rb[4][4];
#pragma unroll
            for (int f = 0; f < 4; f++) ldsm4(ra[f], da + offA[kk][f]);
#pragma unroll
            for (int g = 0; g < 4; g++) ldsm4(rb[g], db + offB[kk][g]);
#pragma unroll
            for (int f = 0; f < 4; f++)
#pragma unroll
                for (int g = 0; g < 4; g++) {
                    mma16816(acc[f][2 * g + 0], ra[f], rb[g][0], rb[g][1]);
                    mma16816(acc[f][2 * g + 1], ra[f], rb[g][2], rb[g][3]);
                }
        }
        __syncthreads();
    }

    // upper tile write (fp16)
    const int col0 = bn + wn * 64 + (lane & 3) * 2;
#pragma unroll
    for (int f = 0; f < 4; f++) {
        const int row0 = bm + wm * 64 + f * 16 + (lane >> 2);
#pragma unroll
        for (int g = 0; g < 8; g++) {
            const int col = col0 + g * 8;
            *(__half2*)(C + (size_t)row0 * Nn + col) =
                __floats2half2_rn(acc[f][g][0], acc[f][g][1]);
            *(__half2*)(C + (size_t)(row0 + 8) * Nn + col) =
                __floats2half2_rn(acc[f][g][2], acc[f][g][3]);
        }
    }

    // mirrored (lower) tile write via smem transpose, coalesced, fp16
    if (bi != bj) {
#pragma unroll
        for (int cc = 0; cc < 2; cc++) {
            __syncthreads();
            float* buf = smT + wn * (32 * 128);
#pragma unroll
            for (int gl = 0; gl < 4; gl++) {
                const int g = cc * 4 + gl;
                const int cl = gl * 8 + (lane & 3) * 2;
#pragma unroll
                for (int f = 0; f < 4; f++) {
                    const int r = wm * 64 + f * 16 + (lane >> 2);
                    buf[cl * 128 + r]           = acc[f][g][0];
                    buf[(cl + 1) * 128 + r]     = acc[f][g][1];
                    buf[cl * 128 + r + 8]       = acc[f][g][2];
                    buf[(cl + 1) * 128 + r + 8] = acc[f][g][3];
                }
            }
            __syncthreads();
            for (int idx = tid; idx < 64 * 32; idx += 128) {
                const int rr = idx >> 5;
                const int sg = idx & 31;
                const int b2 = rr >> 5;
                const int cl = rr & 31;
                const int cAbs = bn + b2 * 64 + cc * 32 + cl;
                float4 v = *(float4*)(smT + b2 * (32 * 128) + cl * 128 + sg * 4);
                union { __half2 h[2]; uint2 u; } cv;
                cv.h[0] = __floats2half2_rn(v.x, v.y);
                cv.h[1] = __floats2half2_rn(v.z, v.w);
                *(uint2*)(C + (size_t)cAbs * Nn + bm + sg * 4) = cv.u;
            }
        }
    }
}

// ---------------- fp32 -> fp16 convert ---------------------------------------
__global__ void split_kernel(const float* __restrict__ x, uint16_t* __restrict__ hi,
                             int n4)
{
    int i = blockIdx.x * blockDim.x + threadIdx.x;
    if (i >= n4) return;
    float4 v = ((const float4*)x)[i];
    ushort4 hv;
    hv.x = __half_as_ushort(__float2half_rn(v.x));
    hv.y = __half_as_ushort(__float2half_rn(v.y));
    hv.z = __half_as_ushort(__float2half_rn(v.z));
    hv.w = __half_as_ushort(__float2half_rn(v.w));
    ((ushort4*)hi)[i] = hv;
}

// ---------------- LayerNorm (fp16 in) -> fp16 act ----------------------------
__global__ void ln_kernel(const float* __restrict__ g0, const float* __restrict__ be0,
                          const float* __restrict__ g1, const float* __restrict__ be1)
{
    int row = blockIdx.x;
    const uint16_t* x = g_seqh + (size_t)row * Dd;
    int tid = threadIdx.x;
    float v0 = __half2float(__ushort_as_half(x[tid]));
    float v1 = __half2float(__ushort_as_half(x[tid + 256]));
    __shared__ float rs[256], rq[256];
    rs[tid] = v0 + v1;
    rq[tid] = v0 * v0 + v1 * v1;
    __syncthreads();
    for (int st = 128; st > 0; st >>= 1) {
        if (tid < st) { rs[tid] += rs[tid + st]; rq[tid] += rq[tid + st]; }
        __syncthreads();
    }
    float mean = rs[0] * (1.f / Dd);
    float var = rq[0] * (1.f / Dd) - mean * mean;
    float inv = rsqrtf(var + 1e-5f);
    const float* gg = (row & 1) ? g1 : g0;
    const float* bb = (row & 1) ? be1 : be0;
    float y0 = (v0 - mean) * inv * gg[tid] + bb[tid];
    float y1 = (v1 - mean) * inv * gg[tid + 256] + bb[tid + 256];
    size_t base = (size_t)row * Dd;
    g_ah[base + tid]       = __half_as_ushort(__float2half_rn(y0));
    g_ah[base + tid + 256] = __half_as_ushort(__float2half_rn(y1));
}

// ---------------- 2-token multihead attention (fp16 qkv) -> ctx fp16 ---------
__global__ void attn_kernel()
{
    int gt = blockIdx.x * blockDim.x + threadIdx.x;
    int gw = gt >> 5, lane = gt & 31;
    if (gw >= Nn * NHEADS) return;
    int node = gw >> 3, h = gw & 7;
    const uint16_t* base = g_qkvh + (size_t)node * 2 * (3 * Dd);
    int d0 = lane * 2;
    float q[2][2], k[2][2], v[2][2];
#pragma unroll
    for (int t = 0; t < 2; t++) {
        const uint16_t* r = base + t * (3 * Dd) + h * HDIM;
        float2 qq = __half22float2(*(const __half2*)(r + d0));
        float2 kk = __half22float2(*(const __half2*)(r + Dd + d0));
        float2 vv = __half22float2(*(const __half2*)(r + 2 * Dd + d0));
        q[t][0] = qq.x; q[t][1] = qq.y;
        k[t][0] = kk.x; k[t][1] = kk.y;
        v[t][0] = vv.x; v[t][1] = vv.y;
    }
    float s[2][2];
#pragma unroll
    for (int qi = 0; qi < 2; qi++)
#pragma unroll
        for (int ki = 0; ki < 2; ki++)
            s[qi][ki] = q[qi][0] * k[ki][0] + q[qi][1] * k[ki][1];
#pragma unroll
    for (int o = 16; o > 0; o >>= 1)
#pragma unroll
        for (int qi = 0; qi < 2; qi++)
#pragma unroll
            for (int ki = 0; ki < 2; ki++)
                s[qi][ki] += __shfl_xor_sync(0xffffffffu, s[qi][ki], o);
    const float scale = 0.125f;
#pragma unroll
    for (int qi = 0; qi < 2; qi++) {
        float a0 = s[qi][0] * scale, a1 = s[qi][1] * scale;
        float m = fmaxf(a0, a1);
        float e0 = __expf(a0 - m), e1 = __expf(a1 - m);
        float inv = 1.f / (e0 + e1);
        float w0 = e0 * inv, w1 = e1 * inv;
        float o0 = w0 * v[0][0] + w1 * v[1][0];
        float o1 = w0 * v[0][1] + w1 * v[1][1];
        size_t off = (size_t)(node * 2 + qi) * Dd + h * HDIM + d0;
        *(__half2*)(g_ah + off) = __floats2half2_rn(o0, o1);
    }
}

// ---------------- softmax stats + top-16 via segment-max hierarchy ----------
__global__ void topk_kernel(float* __restrict__ Hout)
{
    int row = blockIdx.x;
    extern __shared__ float sh[];                 // Nn floats + 256 segmax
    float* segmax = sh + Nn;
    __shared__ float swv[8];
    __shared__ int swi[8];
    __shared__ float s_bcast;
    __shared__ int s_seg;
    __shared__ float topv[TOPK];
    __shared__ int topi[TOPK];
    const uint16_t* srow = g_Sh + (size_t)row * Nn;
    int tid = threadIdx.x;
    int lane = tid & 31, wid = tid >> 5;

    for (int j8 = tid; j8 < Nn / 8; j8 += 256) {
        uint4 raw = ((const uint4*)srow)[j8];
        float2 f0 = __half22float2(*(__half2*)&raw.x);
        float2 f1 = __half22float2(*(__half2*)&raw.y);
        float2 f2 = __half22float2(*(__half2*)&raw.z);
        float2 f3 = __half22float2(*(__half2*)&raw.w);
        float4 o0 = make_float4(f0.x, f0.y, f1.x, f1.y);
        float4 o1 = make_float4(f2.x, f2.y, f3.x, f3.y);
        *(float4*)(sh + j8 * 8)     = o0;
        *(float4*)(sh + j8 * 8 + 4) = o1;
    }
    __syncthreads();

    {
        const int base = tid * 32;
        float sm = -INFINITY;
#pragma unroll 8
        for (int i = 0; i < 32; i++)
            sm = fmaxf(sm, sh[base + ((i + tid) & 31)]);
        segmax[tid] = sm;
        float lmax = sm;
#pragma unroll
        for (int o = 16; o > 0; o >>= 1)
            lmax = fmaxf(lmax, __shfl_xor_sync(0xffffffffu, lmax, o));
        if (lane == 0) swv[wid] = lmax;
    }
    __syncthreads();
    if (tid == 0) {
        float m = swv[0];
#pragma unroll
        for (int w = 1; w < 8; w++) m = fmaxf(m, swv[w]);
        s_bcast = m;
    }
    __syncthreads();
    const float rmax = s_bcast;

    float lsum = 0.f;
    for (int j4 = tid; j4 < Nn / 4; j4 += 256) {
        float4 v = *(float4*)(sh + j4 * 4);
        lsum += __expf(v.x - rmax) + __expf(v.y - rmax)
              + __expf(v.z - rmax) + __expf(v.w - rmax);
    }
#pragma unroll
    for (int o = 16; o > 0; o >>= 1)
        lsum += __shfl_xor_sync(0xffffffffu, lsum, o);
    if (lane == 0) swv[wid] = lsum;
    __syncthreads();
    if (tid == 0) {
        float s = 0.f;
#pragma unroll
        for (int w = 0; w < 8; w++) s += swv[w];
        s_bcast = 1.f / s;
    }
    __syncthreads();
    const float rinv = s_bcast;

    for (int kk = 0; kk < TOPK; kk++) {
        float v = segmax[tid];
        int idx = tid;
#pragma unroll
        for (int o = 16; o > 0; o >>= 1) {
            float ov = __shfl_xor_sync(0xffffffffu, v, o);
            int oi = __shfl_xor_sync(0xffffffffu, idx, o);
            if (ov > v || (ov == v && oi < idx)) { v = ov; idx = oi; }
        }
        if (lane == 0) { swv[wid] = v; swi[wid] = idx; }
        __syncthreads();
        if (tid == 0) {
            float bv = swv[0]; int bi = swi[0];
#pragma unroll
            for (int w = 1; w < 8; w++)
                if (swv[w] > bv || (swv[w] == bv && swi[w] < bi)) { bv = swv[w]; bi = swi[w]; }
            s_seg = bi;
        }
        __syncthreads();
        const int s = s_seg;
        if (wid == 0) {
            int ei = s * 32 + lane;
            float ev = sh[ei];
            float v2 = ev; int i2 = ei;
#pragma unroll
            for (int o = 16; o > 0; o >>= 1) {
                float ov = __shfl_xor_sync(0xffffffffu, v2, o);
                int oi = __shfl_xor_sync(0xffffffffu, i2, o);
                if (ov > v2 || (ov == v2 && oi < i2)) { v2 = ov; i2 = oi; }
            }
            if (lane == 0) { topv[kk] = v2; topi[kk] = i2; }
            float nv = (ei == i2) ? -INFINITY : ev;
            if (ei == i2) sh[ei] = -INFINITY;
            float mx = nv;
#pragma unroll
            for (int o = 16; o > 0; o >>= 1)
                mx = fmaxf(mx, __shfl_xor_sync(0xffffffffu, mx, o));
            if (lane == 0) segmax[s] = mx;
        }
        __syncthreads();
    }

    if (tid == 0) {
        Hout[(size_t)row * Nn + row] = 1.0f;
#pragma unroll
        for (int kk = 0; kk < TOPK; kk++)
            Hout[(size_t)topi[kk] * Nn + row] = __expf(topv[kk] - rmax) * rinv;
    }
}

__global__ void ew_kernel(const float* __restrict__ w2, const float* __restrict__ b2,
                          float* __restrict__ out)
{
    int gt = blockIdx.x * blockDim.x + threadIdx.x;
    int gw = gt >> 5, lane = gt & 31;
    if (gw >= Nn) return;
    const float* hrow = g_hidden + (size_t)gw * (Dd / 2);
    float s = 0.f;
    for (int j = lane; j < Dd / 2; j += 32) s += hrow[j] * w2[j];
#pragma unroll
    for (int o = 16; o > 0; o >>= 1) s += __shfl_xor_sync(0xffffffffu, s, o);
    if (lane == 0) {
        float v = s + b2[0];
        float sig = 1.f / (1.f + __expf(-v));
        out[gw] = fmaxf(sig, 1e-8f);
    }
}

// ---------------- launch ------------------------------------------------------
static void do_split_s(const float* src, uint16_t* hi, size_t n, cudaStream_t st)
{
    int n4 = (int)(n / 4);
    split_kernel<<<(n4 + 255) / 256, 256, 0, st>>>(src, hi, n4);
}

extern "C" void kernel_launch(void* const* d_in, const int* in_sizes, int n_in,
                              void* d_out, int out_size)
{
    const float* x0    = (const float*)d_in[0];
    const float* x1    = (const float*)d_in[1];
    const float* w_p0  = (const float*)d_in[2];
    const float* b_p0  = (const float*)d_in[3];
    const float* gg0   = (const float*)d_in[4];
    const float* be0   = (const float*)d_in[5];
    const float* w_p1  = (const float*)d_in[6];
    const float* b_p1  = (const float*)d_in[7];
    const float* gg1   = (const float*)d_in[8];
    const float* be1   = (const float*)d_in[9];
    const float* in_w  = (const float*)d_in[10];
    const float* in_b  = (const float*)d_in[11];
    const float* out_w = (const float*)d_in[12];
    const float* out_b = (const float*)d_in[13];
    const float* ew_w1 = (const float*)d_in[14];
    const float* ew_b1 = (const float*)d_in[15];
    const float* ew_w2 = (const float*)d_in[16];
    const float* ew_b2 = (const float*)d_in[17];

    float* H  = (float*)d_out;
    float* ew = H + (size_t)Nn * Nn;

    float *hidden;
    uint16_t *seqh, *qkvh, *Sh;
    uint16_t *ah, *a1h, *fh;
    uint16_t *wp0h, *wp1h, *wqh, *woh, *weh;
    cudaGetSymbolAddress((void**)&seqh, g_seqh);
    cudaGetSymbolAddress((void**)&qkvh, g_qkvh);
    cudaGetSymbolAddress((void**)&Sh, g_Sh);
    cudaGetSymbolAddress((void**)&hidden, g_hidden);
    cudaGetSymbolAddress((void**)&ah, g_ah);
    cudaGetSymbolAddress((void**)&a1h, g_a1h);
    cudaGetSymbolAddress((void**)&wp0h, g_wp0h);
    cudaGetSymbolAddress((void**)&wp1h, g_wp1h);
    cudaGetSymbolAddress((void**)&wqh, g_wqh);
    cudaGetSymbolAddress((void**)&woh, g_woh);
    cudaGetSymbolAddress((void**)&weh, g_weh);
    cudaGetSymbolAddress((void**)&fh, g_fh);

    static cudaStream_t s1 = nullptr, s2 = nullptr;
    static cudaEvent_t eF = nullptr, eS2 = nullptr, eP1 = nullptr, eM = nullptr, eE = nullptr;
    if (!s1) {
        cudaStreamCreateWithFlags(&s1, cudaStreamNonBlocking);
        cudaStreamCreateWithFlags(&s2, cudaStreamNonBlocking);
        cudaEventCreateWithFlags(&eF,  cudaEventDisableTiming);
        cudaEventCreateWithFlags(&eS2, cudaEventDisableTiming);
        cudaEventCreateWithFlags(&eP1, cudaEventDisableTiming);
        cudaEventCreateWithFlags(&eM,  cudaEventDisableTiming);
        cudaEventCreateWithFlags(&eE,  cudaEventDisableTiming);
    }

    // fork from capture (default) stream
    cudaEventRecord(eF, 0);
    cudaStreamWaitEvent(s1, eF, 0);
    cudaStreamWaitEvent(s2, eF, 0);

    // s2: H memset + weight converts (input-only)
    cudaMemsetAsync(H, 0, (size_t)Nn * Nn * sizeof(float), s2);
    do_split_s(in_w,  wqh, (size_t)3 * Dd * Dd, s2);
    do_split_s(out_w, woh, (size_t)Dd * Dd, s2);
    do_split_s(ew_w1, weh, (size_t)(Dd / 2) * Dd, s2);
    cudaEventRecord(eS2, s2);

    // s1: modality-1 projection chain (fp16 out into interleaved seqh)
    do_split_s(x1,   a1h,  (size_t)Nn * Dd, s1);
    do_split_s(w_p1, wp1h, (size_t)Dd * Dd, s1);
    tgemm<1, 1, 1><<<dim3(Dd / 128, Nn / 128), 128, 0, s1>>>(a1h, wp1h, b_p1, seqh + Dd, 2 * Dd);
    cudaEventRecord(eP1, s1);

    // stream 0: modality-0 projection chain
    do_split_s(x0,   ah,   (size_t)Nn * Dd, 0);
    do_split_s(w_p0, wp0h, (size_t)Dd * Dd, 0);
    tgemm<1, 1, 1><<<dim3(Dd / 128, Nn / 128), 128>>>(ah, wp0h, b_p0, seqh, 2 * Dd);

    // join proj1 + weight converts, trunk on stream 0
    cudaStreamWaitEvent(0, eP1, 0);
    ln_kernel<<<2 * Nn, 256>>>(gg0, be0, gg1, be1);
    cudaStreamWaitEvent(0, eS2, 0);
    tgemm<0, 1, 1><<<dim3(3 * Dd / 128, 2 * Nn / 128), 128>>>(ah, wqh, in_b, qkvh, 3 * Dd);
    attn_kernel<<<(Nn * NHEADS * 32) / 256, 256>>>();
    // out-proj with fused token-mean: writes fused fp16 directly (node rows)
    tgemm<0, 1, 1, 1><<<dim3(Dd / 128, 2 * Nn / 128), 128>>>(ah, woh, out_b, fh, Dd);
    cudaEventRecord(eM, 0);

    // s1: edge-weight MLP (parallel to sim GEMM + topk)
    cudaStreamWaitEvent(s1, eM, 0);
    tgemm<1, 1, 0><<<dim3((Dd / 2) / 128, Nn / 128), 128, 0, s1>>>(fh, weh, ew_b1, hidden, Dd / 2);
    ew_kernel<<<(Nn * 32) / 256, 256, 0, s1>>>(ew_w2, ew_b2, ew);
    cudaEventRecord(eE, s1);

    // stream 0: similarity GEMM (symmetric, fp16 S) + topk
    tgemm_sym<<<(Nn / 128) * (Nn / 128 + 1) / 2, 128>>>(fh, Sh);
    topk_kernel<<<Nn, 256, (Nn + 256) * sizeof(float)>>>(H);

    // join ew branch back into capture stream
    cudaStreamWaitEvent(0, eE, 0);
}